// round 1
// baseline (speedup 1.0000x reference)
#include <cuda_runtime.h>
#include <math.h>

// Problem dims (fixed by the reference)
#define B_  8
#define S_  2048
#define D_  64
#define H_  4096

// Scratch (alloc-free rule: __device__ globals).
// g_scores holds scores, then adjusted logits, then softmax(attn) in place.
__device__ float g_scores[(size_t)B_ * S_ * S_];   // 128 MB
__device__ float g_h[(size_t)B_ * S_ * H_];        // 256 MB

// ---------------------------------------------------------------------------
// Kernel 1: scores[b,q,k] = dot(Q[b,q,:], K[b,k,:]) / 8
// 64x64 output tile per block, whole d=64 depth in smem (no k-loop).
// ---------------------------------------------------------------------------
__global__ __launch_bounds__(256)
void qk_kernel(const float* __restrict__ Q, const float* __restrict__ Km,
               float* __restrict__ S) {
    __shared__ float Qs[64][65];
    __shared__ float Ks[64][65];
    const int b  = blockIdx.z;
    const int q0 = blockIdx.y * 64;
    const int k0 = blockIdx.x * 64;
    const int tid = threadIdx.x;

    const float* Qb = Q  + ((size_t)b * S_ + q0) * D_;
    const float* Kb = Km + ((size_t)b * S_ + k0) * D_;

    // 64 rows x 64 cols each = 1024 float4 per tile, 256 threads -> 4 iters
    #pragma unroll
    for (int i = tid; i < 64 * 16; i += 256) {
        int r = i >> 4;
        int c = (i & 15) * 4;
        float4 v = *(const float4*)(Qb + (size_t)r * D_ + c);
        Qs[r][c] = v.x; Qs[r][c + 1] = v.y; Qs[r][c + 2] = v.z; Qs[r][c + 3] = v.w;
        float4 w = *(const float4*)(Kb + (size_t)r * D_ + c);
        Ks[r][c] = w.x; Ks[r][c + 1] = w.y; Ks[r][c + 2] = w.z; Ks[r][c + 3] = w.w;
    }
    __syncthreads();

    const int tx = tid & 15;   // col group
    const int ty = tid >> 4;   // row group
    float acc[4][4] = {};
    #pragma unroll 8
    for (int d = 0; d < 64; d++) {
        float a[4], bb[4];
        #pragma unroll
        for (int i = 0; i < 4; i++) a[i]  = Qs[ty * 4 + i][d];
        #pragma unroll
        for (int j = 0; j < 4; j++) bb[j] = Ks[tx * 4 + j][d];
        #pragma unroll
        for (int i = 0; i < 4; i++)
            #pragma unroll
            for (int j = 0; j < 4; j++)
                acc[i][j] = fmaf(a[i], bb[j], acc[i][j]);
    }

    #pragma unroll
    for (int i = 0; i < 4; i++) {
        float4 o;
        o.x = acc[i][0] * 0.125f;
        o.y = acc[i][1] * 0.125f;
        o.z = acc[i][2] * 0.125f;
        o.w = acc[i][3] * 0.125f;
        *(float4*)(S + ((size_t)b * S_ + q0 + ty * 4 + i) * S_ + k0 + tx * 4) = o;
    }
}

// ---------------------------------------------------------------------------
// Kernel 2/3: generic batched NN GEMM with bias (+ optional ReLU).
// C[z] = act(A[z] @ Bmat + bias).  A: [M,Kd] per batch, Bmat: [Kd,N] shared.
// 128x128 block tile, BK=16, 256 threads, 8x8 per-thread micro-tile.
// ---------------------------------------------------------------------------
template <bool RELU>
__global__ __launch_bounds__(256)
void gemm_bias_kernel(const float* __restrict__ A, const float* __restrict__ Bm,
                      const float* __restrict__ bias, float* __restrict__ C,
                      int M, int N, int Kd) {
    const int BM = 128, BN = 128, BK = 16;
    __shared__ float As[BK][BM + 4];   // transposed A tile, padded
    __shared__ float Bs[BK][BN];

    A += (size_t)blockIdx.z * M * Kd;
    C += (size_t)blockIdx.z * M * N;

    const int cRow = blockIdx.y * BM;
    const int cCol = blockIdx.x * BN;
    const int tid  = threadIdx.x;

    // loader indices
    const int aRow = tid >> 2;          // 0..63
    const int aCol = (tid & 3) * 4;     // 0,4,8,12
    const int bRow = tid >> 5;          // 0..7
    const int bCol = (tid & 31) * 4;    // 0..124

    // compute indices
    const int tx = tid & 15;            // col group (x8)
    const int ty = tid >> 4;            // row group (x8)

    float acc[8][8] = {};
    float regA[8], regB[8];

    for (int k0 = 0; k0 < Kd; k0 += BK) {
        // A tile: 128x16, stored transposed
        #pragma unroll
        for (int r = 0; r < 2; r++) {
            float4 v = *(const float4*)(A + (size_t)(cRow + aRow + r * 64) * Kd + k0 + aCol);
            As[aCol + 0][aRow + r * 64] = v.x;
            As[aCol + 1][aRow + r * 64] = v.y;
            As[aCol + 2][aRow + r * 64] = v.z;
            As[aCol + 3][aRow + r * 64] = v.w;
        }
        // B tile: 16x128, direct
        #pragma unroll
        for (int r = 0; r < 2; r++) {
            float4 v = *(const float4*)(Bm + (size_t)(k0 + bRow + r * 8) * N + cCol + bCol);
            *(float4*)&Bs[bRow + r * 8][bCol] = v;
        }
        __syncthreads();

        #pragma unroll
        for (int kk = 0; kk < BK; kk++) {
            *(float4*)&regA[0] = *(const float4*)&As[kk][ty * 8];
            *(float4*)&regA[4] = *(const float4*)&As[kk][ty * 8 + 4];
            *(float4*)&regB[0] = *(const float4*)&Bs[kk][tx * 8];
            *(float4*)&regB[4] = *(const float4*)&Bs[kk][tx * 8 + 4];
            #pragma unroll
            for (int i = 0; i < 8; i++)
                #pragma unroll
                for (int j = 0; j < 8; j++)
                    acc[i][j] = fmaf(regA[i], regB[j], acc[i][j]);
        }
        __syncthreads();
    }

    // epilogue: bias (+ relu), vectorized stores
    #pragma unroll
    for (int i = 0; i < 8; i++) {
        float* Cp = C + (size_t)(cRow + ty * 8 + i) * N + cCol + tx * 8;
        #pragma unroll
        for (int j = 0; j < 8; j += 4) {
            float4 bv = *(const float4*)(bias + cCol + tx * 8 + j);
            float4 o;
            o.x = acc[i][j + 0] + bv.x;
            o.y = acc[i][j + 1] + bv.y;
            o.z = acc[i][j + 2] + bv.z;
            o.w = acc[i][j + 3] + bv.w;
            if (RELU) {
                o.x = fmaxf(o.x, 0.f); o.y = fmaxf(o.y, 0.f);
                o.z = fmaxf(o.z, 0.f); o.w = fmaxf(o.w, 0.f);
            }
            *(float4*)(Cp + j) = o;
        }
    }
}

// ---------------------------------------------------------------------------
// Kernel 4: row softmax over S_=2048, in place. One 256-thread block per row.
// ---------------------------------------------------------------------------
__global__ __launch_bounds__(256)
void softmax_kernel(float* __restrict__ X) {
    __shared__ float red[8];
    float* x = X + (size_t)blockIdx.x * S_;
    const int tid = threadIdx.x;
    const int wid = tid >> 5, lane = tid & 31;

    float4 v0 = ((const float4*)x)[tid];
    float4 v1 = ((const float4*)x)[tid + 256];

    // max
    float m = fmaxf(fmaxf(fmaxf(v0.x, v0.y), fmaxf(v0.z, v0.w)),
                    fmaxf(fmaxf(v1.x, v1.y), fmaxf(v1.z, v1.w)));
    #pragma unroll
    for (int o = 16; o > 0; o >>= 1) m = fmaxf(m, __shfl_xor_sync(0xffffffffu, m, o));
    if (lane == 0) red[wid] = m;
    __syncthreads();
    if (tid < 32) {
        float t = (tid < 8) ? red[tid] : -INFINITY;
        #pragma unroll
        for (int o = 4; o > 0; o >>= 1) t = fmaxf(t, __shfl_xor_sync(0xffffffffu, t, o));
        if (tid == 0) red[0] = t;
    }
    __syncthreads();
    m = red[0];
    __syncthreads();

    // exp + sum
    v0.x = __expf(v0.x - m); v0.y = __expf(v0.y - m);
    v0.z = __expf(v0.z - m); v0.w = __expf(v0.w - m);
    v1.x = __expf(v1.x - m); v1.y = __expf(v1.y - m);
    v1.z = __expf(v1.z - m); v1.w = __expf(v1.w - m);
    float s = (v0.x + v0.y + v0.z + v0.w) + (v1.x + v1.y + v1.z + v1.w);
    #pragma unroll
    for (int o = 16; o > 0; o >>= 1) s += __shfl_xor_sync(0xffffffffu, s, o);
    if (lane == 0) red[wid] = s;
    __syncthreads();
    if (tid < 32) {
        float t = (tid < 8) ? red[tid] : 0.f;
        #pragma unroll
        for (int o = 4; o > 0; o >>= 1) t += __shfl_xor_sync(0xffffffffu, t, o);
        if (tid == 0) red[0] = t;
    }
    __syncthreads();
    const float inv = 1.0f / red[0];

    v0.x *= inv; v0.y *= inv; v0.z *= inv; v0.w *= inv;
    v1.x *= inv; v1.y *= inv; v1.z *= inv; v1.w *= inv;
    ((float4*)x)[tid] = v0;
    ((float4*)x)[tid + 256] = v1;
}

// ---------------------------------------------------------------------------
// Kernel 5: out[b,q,:] = attn[b,q,:] @ V[b,:,:].  64 threads per q-row (one
// per d), 4 rows per 256-thread block. attn row is warp-broadcast; V is
// coalesced and L2-resident (512 KB per batch).
// ---------------------------------------------------------------------------
__global__ __launch_bounds__(256)
void av_kernel(const float* __restrict__ attn, const float* __restrict__ V,
               float* __restrict__ out) {
    const int b    = blockIdx.y;
    const int q    = blockIdx.x * 4 + (threadIdx.x >> 6);
    const int lane = threadIdx.x & 63;          // d index

    const float* arow = attn + ((size_t)b * S_ + q) * S_;
    const float* Vb   = V + (size_t)b * S_ * D_ + lane;

    float acc = 0.f;
    #pragma unroll 4
    for (int k = 0; k < S_; k += 4) {
        float4 s = *(const float4*)(arow + k);
        acc = fmaf(s.x, Vb[(size_t)(k + 0) * D_], acc);
        acc = fmaf(s.y, Vb[(size_t)(k + 1) * D_], acc);
        acc = fmaf(s.z, Vb[(size_t)(k + 2) * D_], acc);
        acc = fmaf(s.w, Vb[(size_t)(k + 3) * D_], acc);
    }
    out[((size_t)b * S_ + q) * D_ + lane] = acc;
}

// ---------------------------------------------------------------------------
// Launch
// ---------------------------------------------------------------------------
extern "C" void kernel_launch(void* const* d_in, const int* in_sizes, int n_in,
                              void* d_out, int out_size) {
    const float* Q  = (const float*)d_in[0];
    const float* K  = (const float*)d_in[1];
    const float* V  = (const float*)d_in[2];
    const float* W1 = (const float*)d_in[3];
    const float* b1 = (const float*)d_in[4];
    const float* W2 = (const float*)d_in[5];
    const float* b2 = (const float*)d_in[6];
    float* out = (float*)d_out;

    float* scores = nullptr;
    float* h      = nullptr;
    cudaGetSymbolAddress((void**)&scores, g_scores);
    cudaGetSymbolAddress((void**)&h, g_h);

    // 1) scores = Q K^T / sqrt(d)
    qk_kernel<<<dim3(S_ / 64, S_ / 64, B_), 256>>>(Q, K, scores);

    // 2) h = relu(scores @ W1 + b1)   [per batch: 2048x4096x2048]
    gemm_bias_kernel<true><<<dim3(H_ / 128, S_ / 128, B_), 256>>>(
        scores, W1, b1, h, S_, H_, S_);

    // 3) adjusted = h @ W2 + b2       [per batch: 2048x2048x4096] -> scores buf
    gemm_bias_kernel<false><<<dim3(S_ / 128, S_ / 128, B_), 256>>>(
        h, W2, b2, scores, S_, S_, H_);

    // 4) softmax rows (in place)
    softmax_kernel<<<B_ * S_, 256>>>(scores);

    // 5) out = attn @ V
    av_kernel<<<dim3(S_ / 4, B_), 256>>>(scores, V, out);
}

// round 3
// speedup vs baseline: 2.3046x; 2.3046x over previous
#include <cuda_runtime.h>
#include <math.h>
#include <stdint.h>

#define B_  8
#define S_  2048
#define D_  64
#define H_  4096

// Scratch (__device__ globals: the sanctioned alloc-free path)
__device__ float g_scores[(size_t)B_ * S_ * S_];   // 128 MB (scores -> logits -> attn)
__device__ float g_h[(size_t)B_ * S_ * H_];        // 256 MB
__device__ float g_w1r[(size_t)S_ * H_];           // 32 MB  tf32-rounded W1 [K,N]
__device__ float g_w2r[(size_t)H_ * S_];           // 32 MB  tf32-rounded W2 [K,N]

// ---------------------------------------------------------------------------
// helpers
// ---------------------------------------------------------------------------
__device__ __forceinline__ float tf32_rn(float x) {
    float r; asm("cvt.rna.tf32.f32 %0, %1;" : "=f"(r) : "f"(x)); return r;
}
__device__ __forceinline__ void cp16(uint32_t dst, const void* src) {
    asm volatile("cp.async.cg.shared.global [%0], [%1], 16;" :: "r"(dst), "l"(src) : "memory");
}
#define CP_COMMIT() asm volatile("cp.async.commit_group;" ::: "memory")
#define CP_WAIT1()  asm volatile("cp.async.wait_group 1;" ::: "memory")
#define CP_WAIT0()  asm volatile("cp.async.wait_group 0;" ::: "memory")

__device__ __forceinline__ uint32_t smem_u32(const void* p) {
    uint32_t a;
    asm("{ .reg .u64 t; cvta.to.shared.u64 t, %1; cvt.u32.u64 %0, t; }" : "=r"(a) : "l"(p));
    return a;
}

#define MMA_TF32(c, a, b)                                                      \
    asm volatile(                                                              \
        "mma.sync.aligned.m16n8k8.row.col.f32.tf32.tf32.f32 "                  \
        "{%0,%1,%2,%3}, {%4,%5,%6,%7}, {%8,%9}, {%0,%1,%2,%3};"                \
        : "+f"((c)[0]), "+f"((c)[1]), "+f"((c)[2]), "+f"((c)[3])               \
        : "r"((a)[0]), "r"((a)[1]), "r"((a)[2]), "r"((a)[3]),                  \
          "r"((b)[0]), "r"((b)[1]))

// ---------------------------------------------------------------------------
// tf32 mma.sync GEMM:  C[z] = act(A[z] @ B + bias)
// A: [M,K] row-major per batch. B: [K,N] row-major (shared across batch).
// CTA tile 128x128, BK=16, 3-stage cp.async, 8 warps (2x4), warp tile 64x32.
// All MMA inputs must be pre-rounded to tf32 (A via producer epilogues, B via
// round_copy) so hardware truncation is exact.
// ---------------------------------------------------------------------------
constexpr int BM = 128, BN = 128, BK = 16, ST = 3;
constexpr int ARS = 20;    // A smem row stride (floats): m-row of 16 k + pad
constexpr int BRS = 136;   // B smem row stride (floats): k-row of 128 n + pad
constexpr int A_ST_BYTES = BM * ARS * 4;                  // 10240
constexpr int B_ST_BYTES = BK * BRS * 4;                  // 8704
constexpr int STAGE_BYTES = A_ST_BYTES + B_ST_BYTES;      // 18944
constexpr int GEMM_SMEM = ST * STAGE_BYTES;               // 56832

__device__ __forceinline__ void load_stage(uint32_t sb, int s, const float* gA,
                                           const float* gB, int K, int N,
                                           int n0, int k0, int tid) {
    const uint32_t aB = sb + s * STAGE_BYTES;
    const uint32_t bB = aB + A_ST_BYTES;
    // A: 128 rows x 4 chunks of 16B
    #pragma unroll
    for (int i = 0; i < 2; i++) {
        int t = i * 256 + tid;
        int r = t >> 2, c = t & 3;
        cp16(aB + (uint32_t)(r * ARS + c * 4) * 4, gA + (size_t)r * K + k0 + c * 4);
    }
    // B: 16 rows x 32 chunks of 16B
    #pragma unroll
    for (int i = 0; i < 2; i++) {
        int t = i * 256 + tid;
        int r = t >> 5, c = t & 31;
        cp16(bB + (uint32_t)(r * BRS + c * 4) * 4, gB + (size_t)(k0 + r) * N + n0 + c * 4);
    }
    CP_COMMIT();
}

template <bool RELU, bool RND>
__global__ __launch_bounds__(256, 1)
void mma_gemm(const float* __restrict__ A, const float* __restrict__ Bm,
              const float* __restrict__ bias, float* __restrict__ C,
              int M, int N, int K) {
    extern __shared__ char smem[];
    const uint32_t sb = smem_u32(smem);
    const int tid = threadIdx.x;
    const int w = tid >> 5, L = tid & 31;
    const int wm = (w >> 2) * 64;          // warp row offset in tile
    const int wn = (w & 3) * 32;           // warp col offset in tile
    const int q = L & 3, r4 = L >> 2;

    const int m0 = blockIdx.y * BM, n0 = blockIdx.x * BN;
    A += (size_t)blockIdx.z * M * K;
    C += (size_t)blockIdx.z * M * N;
    const float* gA = A + (size_t)m0 * K;
    const int NC = K / BK;

    float c[4][4][4] = {};   // [mt][nt][frag]

    load_stage(sb, 0, gA, Bm, K, N, n0, 0, tid);
    load_stage(sb, 1, gA, Bm, K, N, n0, BK, tid);

    for (int cc = 0; cc < NC; cc++) {
        if (cc == NC - 1) { CP_WAIT0(); } else { CP_WAIT1(); }
        __syncthreads();
        if (cc + 2 < NC)
            load_stage(sb, (cc + 2) % ST, gA, Bm, K, N, n0, (cc + 2) * BK, tid);

        const int s = cc % ST;
        const uint32_t* Asu = (const uint32_t*)(smem + s * STAGE_BYTES);
        const uint32_t* Bsu = (const uint32_t*)(smem + s * STAGE_BYTES + A_ST_BYTES);

        #pragma unroll
        for (int ks = 0; ks < 2; ks++) {
            const int kb = ks * 8 + q;
            uint32_t af[4][4], bf[4][2];
            #pragma unroll
            for (int mt = 0; mt < 4; mt++) {
                const int m = wm + mt * 16 + r4;
                af[mt][0] = Asu[m * ARS + kb];
                af[mt][1] = Asu[(m + 8) * ARS + kb];
                af[mt][2] = Asu[m * ARS + kb + 4];
                af[mt][3] = Asu[(m + 8) * ARS + kb + 4];
            }
            #pragma unroll
            for (int nt = 0; nt < 4; nt++) {
                const int n = wn + nt * 8 + r4;
                bf[nt][0] = Bsu[kb * BRS + n];
                bf[nt][1] = Bsu[(kb + 4) * BRS + n];
            }
            #pragma unroll
            for (int mt = 0; mt < 4; mt++)
                #pragma unroll
                for (int nt = 0; nt < 4; nt++)
                    MMA_TF32(c[mt][nt], af[mt], bf[nt]);
        }
        __syncthreads();
    }

    // epilogue: bias (+relu) (+tf32 round), float2 stores
    #pragma unroll
    for (int mt = 0; mt < 4; mt++) {
        #pragma unroll
        for (int nt = 0; nt < 4; nt++) {
            const int col = n0 + wn + nt * 8 + q * 2;
            const float2 bv = *(const float2*)(bias + col);
            #pragma unroll
            for (int hh = 0; hh < 2; hh++) {
                const int row = m0 + wm + mt * 16 + r4 + hh * 8;
                float2 o;
                o.x = c[mt][nt][hh * 2 + 0] + bv.x;
                o.y = c[mt][nt][hh * 2 + 1] + bv.y;
                if (RELU) { o.x = fmaxf(o.x, 0.f); o.y = fmaxf(o.y, 0.f); }
                if (RND)  { o.x = tf32_rn(o.x);    o.y = tf32_rn(o.y); }
                *(float2*)(C + (size_t)row * N + col) = o;
            }
        }
    }
}

// ---------------------------------------------------------------------------
// round_copy: out[i] = tf32(in[i])  (vectorized)
// ---------------------------------------------------------------------------
__global__ __launch_bounds__(256)
void round_copy(const float* __restrict__ in, float* __restrict__ out, int n4) {
    int i = blockIdx.x * 256 + threadIdx.x;
    if (i < n4) {
        float4 v = ((const float4*)in)[i];
        v.x = tf32_rn(v.x); v.y = tf32_rn(v.y);
        v.z = tf32_rn(v.z); v.w = tf32_rn(v.w);
        ((float4*)out)[i] = v;
    }
}

// ---------------------------------------------------------------------------
// QK^T / sqrt(d), output rounded to tf32 (feeds tf32 MMA)
// ---------------------------------------------------------------------------
__global__ __launch_bounds__(256)
void qk_kernel(const float* __restrict__ Q, const float* __restrict__ Km,
               float* __restrict__ S) {
    __shared__ float Qs[64][65];
    __shared__ float Ks[64][65];
    const int b  = blockIdx.z;
    const int q0 = blockIdx.y * 64;
    const int k0 = blockIdx.x * 64;
    const int tid = threadIdx.x;

    const float* Qb = Q  + ((size_t)b * S_ + q0) * D_;
    const float* Kb = Km + ((size_t)b * S_ + k0) * D_;

    #pragma unroll
    for (int i = tid; i < 64 * 16; i += 256) {
        int r = i >> 4;
        int c = (i & 15) * 4;
        float4 v = *(const float4*)(Qb + (size_t)r * D_ + c);
        Qs[r][c] = v.x; Qs[r][c + 1] = v.y; Qs[r][c + 2] = v.z; Qs[r][c + 3] = v.w;
        float4 w = *(const float4*)(Kb + (size_t)r * D_ + c);
        Ks[r][c] = w.x; Ks[r][c + 1] = w.y; Ks[r][c + 2] = w.z; Ks[r][c + 3] = w.w;
    }
    __syncthreads();

    const int tx = tid & 15;
    const int ty = tid >> 4;
    float acc[4][4] = {};
    #pragma unroll 8
    for (int d = 0; d < 64; d++) {
        float a[4], bb[4];
        #pragma unroll
        for (int i = 0; i < 4; i++) a[i]  = Qs[ty * 4 + i][d];
        #pragma unroll
        for (int j = 0; j < 4; j++) bb[j] = Ks[tx * 4 + j][d];
        #pragma unroll
        for (int i = 0; i < 4; i++)
            #pragma unroll
            for (int j = 0; j < 4; j++)
                acc[i][j] = fmaf(a[i], bb[j], acc[i][j]);
    }

    #pragma unroll
    for (int i = 0; i < 4; i++) {
        float4 o;
        o.x = tf32_rn(acc[i][0] * 0.125f);
        o.y = tf32_rn(acc[i][1] * 0.125f);
        o.z = tf32_rn(acc[i][2] * 0.125f);
        o.w = tf32_rn(acc[i][3] * 0.125f);
        *(float4*)(S + ((size_t)b * S_ + q0 + ty * 4 + i) * S_ + k0 + tx * 4) = o;
    }
}

// ---------------------------------------------------------------------------
// Row softmax over S_=2048, in place
// ---------------------------------------------------------------------------
__global__ __launch_bounds__(256)
void softmax_kernel(float* __restrict__ X) {
    __shared__ float red[8];
    float* x = X + (size_t)blockIdx.x * S_;
    const int tid = threadIdx.x;
    const int wid = tid >> 5, lane = tid & 31;

    float4 v0 = ((const float4*)x)[tid];
    float4 v1 = ((const float4*)x)[tid + 256];

    float m = fmaxf(fmaxf(fmaxf(v0.x, v0.y), fmaxf(v0.z, v0.w)),
                    fmaxf(fmaxf(v1.x, v1.y), fmaxf(v1.z, v1.w)));
    #pragma unroll
    for (int o = 16; o > 0; o >>= 1) m = fmaxf(m, __shfl_xor_sync(0xffffffffu, m, o));
    if (lane == 0) red[wid] = m;
    __syncthreads();
    if (tid < 32) {
        float t = (tid < 8) ? red[tid] : -INFINITY;
        #pragma unroll
        for (int o = 4; o > 0; o >>= 1) t = fmaxf(t, __shfl_xor_sync(0xffffffffu, t, o));
        if (tid == 0) red[0] = t;
    }
    __syncthreads();
    m = red[0];
    __syncthreads();

    v0.x = __expf(v0.x - m); v0.y = __expf(v0.y - m);
    v0.z = __expf(v0.z - m); v0.w = __expf(v0.w - m);
    v1.x = __expf(v1.x - m); v1.y = __expf(v1.y - m);
    v1.z = __expf(v1.z - m); v1.w = __expf(v1.w - m);
    float s = (v0.x + v0.y + v0.z + v0.w) + (v1.x + v1.y + v1.z + v1.w);
    #pragma unroll
    for (int o = 16; o > 0; o >>= 1) s += __shfl_xor_sync(0xffffffffu, s, o);
    if (lane == 0) red[wid] = s;
    __syncthreads();
    if (tid < 32) {
        float t = (tid < 8) ? red[tid] : 0.f;
        #pragma unroll
        for (int o = 4; o > 0; o >>= 1) t += __shfl_xor_sync(0xffffffffu, t, o);
        if (tid == 0) red[0] = t;
    }
    __syncthreads();
    const float inv = 1.0f / red[0];

    v0.x *= inv; v0.y *= inv; v0.z *= inv; v0.w *= inv;
    v1.x *= inv; v1.y *= inv; v1.z *= inv; v1.w *= inv;
    ((float4*)x)[tid] = v0;
    ((float4*)x)[tid + 256] = v1;
}

// ---------------------------------------------------------------------------
// out[b,q,:] = attn[b,q,:] @ V[b,:,:]
// ---------------------------------------------------------------------------
__global__ __launch_bounds__(256)
void av_kernel(const float* __restrict__ attn, const float* __restrict__ V,
               float* __restrict__ out) {
    const int b    = blockIdx.y;
    const int q    = blockIdx.x * 4 + (threadIdx.x >> 6);
    const int lane = threadIdx.x & 63;

    const float* arow = attn + ((size_t)b * S_ + q) * S_;
    const float* Vb   = V + (size_t)b * S_ * D_ + lane;

    float acc = 0.f;
    #pragma unroll 4
    for (int k = 0; k < S_; k += 4) {
        float4 s = *(const float4*)(arow + k);
        acc = fmaf(s.x, Vb[(size_t)(k + 0) * D_], acc);
        acc = fmaf(s.y, Vb[(size_t)(k + 1) * D_], acc);
        acc = fmaf(s.z, Vb[(size_t)(k + 2) * D_], acc);
        acc = fmaf(s.w, Vb[(size_t)(k + 3) * D_], acc);
    }
    out[((size_t)b * S_ + q) * D_ + lane] = acc;
}

// ---------------------------------------------------------------------------
// Launch
// ---------------------------------------------------------------------------
extern "C" void kernel_launch(void* const* d_in, const int* in_sizes, int n_in,
                              void* d_out, int out_size) {
    const float* Q  = (const float*)d_in[0];
    const float* K  = (const float*)d_in[1];
    const float* V  = (const float*)d_in[2];
    const float* W1 = (const float*)d_in[3];
    const float* b1 = (const float*)d_in[4];
    const float* W2 = (const float*)d_in[5];
    const float* b2 = (const float*)d_in[6];
    float* out = (float*)d_out;

    float *scores, *h, *w1r, *w2r;
    cudaGetSymbolAddress((void**)&scores, g_scores);
    cudaGetSymbolAddress((void**)&h, g_h);
    cudaGetSymbolAddress((void**)&w1r, g_w1r);
    cudaGetSymbolAddress((void**)&w2r, g_w2r);

    cudaFuncSetAttribute(mma_gemm<true, true>,
                         cudaFuncAttributeMaxDynamicSharedMemorySize, GEMM_SMEM);
    cudaFuncSetAttribute(mma_gemm<false, false>,
                         cudaFuncAttributeMaxDynamicSharedMemorySize, GEMM_SMEM);

    // 0) tf32-rounded weights (unbiased RN; MMA truncation then exact)
    const int nW = S_ * H_ / 4;
    round_copy<<<(nW + 255) / 256, 256>>>(W1, w1r, nW);
    round_copy<<<(nW + 255) / 256, 256>>>(W2, w2r, nW);

    // 1) scores = tf32(Q K^T / sqrt(d))
    qk_kernel<<<dim3(S_ / 64, S_ / 64, B_), 256>>>(Q, K, scores);

    // 2) h = tf32(relu(scores @ W1 + b1))   [tensor core tf32]
    mma_gemm<true, true><<<dim3(H_ / BN, S_ / BM, B_), 256, GEMM_SMEM>>>(
        scores, w1r, b1, h, S_, H_, S_);

    // 3) logits = h @ W2 + b2 -> scores buffer   [tensor core tf32]
    mma_gemm<false, false><<<dim3(S_ / BN, S_ / BM, B_), 256, GEMM_SMEM>>>(
        h, w2r, b2, scores, S_, S_, H_);

    // 4) softmax rows (in place)
    softmax_kernel<<<B_ * S_, 256>>>(scores);

    // 5) out = attn @ V
    av_kernel<<<dim3(S_ / 4, B_), 256>>>(scores, V, out);
}

// round 6
// speedup vs baseline: 2.9739x; 1.2904x over previous
#include <cuda_runtime.h>
#include <math.h>
#include <stdint.h>

#define B_  8
#define S_  2048
#define D_  64
#define H_  4096

// Scratch (__device__ globals: the sanctioned alloc-free path)
__device__ float g_scores[(size_t)B_ * S_ * S_];   // 128 MB (scores -> logits -> attn)
__device__ float g_h[(size_t)B_ * S_ * H_];        // 256 MB
__device__ float g_w1r[(size_t)S_ * H_];           // 32 MB  tf32-rounded W1 [K,N]
__device__ float g_w2r[(size_t)H_ * S_];           // 32 MB  tf32-rounded W2 [K,N]

// ---------------------------------------------------------------------------
// helpers
// ---------------------------------------------------------------------------
__device__ __forceinline__ float tf32_rn(float x) {
    float r; asm("cvt.rna.tf32.f32 %0, %1;" : "=f"(r) : "f"(x)); return r;
}
__device__ __forceinline__ void cp16(uint32_t dst, const void* src) {
    asm volatile("cp.async.cg.shared.global [%0], [%1], 16;" :: "r"(dst), "l"(src) : "memory");
}
#define CP_COMMIT() asm volatile("cp.async.commit_group;" ::: "memory")
#define CP_WAIT1()  asm volatile("cp.async.wait_group 1;" ::: "memory")
#define CP_WAIT0()  asm volatile("cp.async.wait_group 0;" ::: "memory")

__device__ __forceinline__ uint32_t smem_u32(const void* p) {
    uint32_t a;
    asm("{ .reg .u64 t; cvta.to.shared.u64 t, %1; cvt.u32.u64 %0, t; }" : "=r"(a) : "l"(p));
    return a;
}

#define MMA_TF32(c, a, b)                                                      \
    asm volatile(                                                              \
        "mma.sync.aligned.m16n8k8.row.col.f32.tf32.tf32.f32 "                  \
        "{%0,%1,%2,%3}, {%4,%5,%6,%7}, {%8,%9}, {%0,%1,%2,%3};"                \
        : "+f"((c)[0]), "+f"((c)[1]), "+f"((c)[2]), "+f"((c)[3])               \
        : "r"((a)[0]), "r"((a)[1]), "r"((a)[2]), "r"((a)[3]),                  \
          "r"((b)[0]), "r"((b)[1]))

// ---------------------------------------------------------------------------
// tf32 mma.sync GEMM:  C[z] = act(A[z] @ B + bias)
// A: [M,K] row-major per batch. B: [K,N] row-major (shared across batch).
// CTA tile 128x128, BK=16, 3-stage cp.async, 8 warps (2x4), warp tile 64x32.
// 2 CTAs/SM (reg-capped) for latency coverage; one barrier per k-chunk.
// ---------------------------------------------------------------------------
constexpr int BM = 128, BN = 128, BK = 16, ST = 3;
constexpr int ARS = 20;    // A smem row stride (floats)
constexpr int BRS = 136;   // B smem row stride (floats)
constexpr int A_ST_BYTES = BM * ARS * 4;                  // 10240
constexpr int B_ST_BYTES = BK * BRS * 4;                  // 8704
constexpr int STAGE_BYTES = A_ST_BYTES + B_ST_BYTES;      // 18944
constexpr int GEMM_SMEM = ST * STAGE_BYTES;               // 56832

__device__ __forceinline__ void load_stage(uint32_t sb, int s, const float* gA,
                                           const float* gB, int K, int N,
                                           int n0, int k0, int tid) {
    const uint32_t aB = sb + s * STAGE_BYTES;
    const uint32_t bB = aB + A_ST_BYTES;
    // A: 128 rows x 4 chunks of 16B
    #pragma unroll
    for (int i = 0; i < 2; i++) {
        int t = i * 256 + tid;
        int r = t >> 2, c = t & 3;
        cp16(aB + (uint32_t)(r * ARS + c * 4) * 4, gA + (size_t)r * K + k0 + c * 4);
    }
    // B: 16 rows x 32 chunks of 16B
    #pragma unroll
    for (int i = 0; i < 2; i++) {
        int t = i * 256 + tid;
        int r = t >> 5, c = t & 31;
        cp16(bB + (uint32_t)(r * BRS + c * 4) * 4, gB + (size_t)(k0 + r) * N + n0 + c * 4);
    }
    CP_COMMIT();
}

template <bool RELU, bool RND>
__global__ __launch_bounds__(256, 2)
void mma_gemm(const float* __restrict__ A, const float* __restrict__ Bm,
              const float* __restrict__ bias, float* __restrict__ C,
              int M, int N, int K) {
    extern __shared__ char smem[];
    const uint32_t sb = smem_u32(smem);
    const int tid = threadIdx.x;
    const int w = tid >> 5, L = tid & 31;
    const int wm = (w >> 2) * 64;          // warp row offset in tile
    const int wn = (w & 3) * 32;           // warp col offset in tile
    const int q = L & 3, r4 = L >> 2;

    const int m0 = blockIdx.y * BM, n0 = blockIdx.x * BN;
    A += (size_t)blockIdx.z * M * K;
    C += (size_t)blockIdx.z * M * N;
    const float* gA = A + (size_t)m0 * K;
    const int NC = K / BK;

    float c[4][4][4] = {};   // [mt][nt][frag]

    load_stage(sb, 0, gA, Bm, K, N, n0, 0, tid);
    load_stage(sb, 1, gA, Bm, K, N, n0, BK, tid);

    for (int cc = 0; cc < NC; cc++) {
        if (cc == NC - 1) { CP_WAIT0(); } else { CP_WAIT1(); }
        __syncthreads();
        // Load targets stage (cc+2)%3 == (cc-1)%3, finished by all warps
        // before the barrier above — safe with a single barrier per chunk.
        if (cc + 2 < NC)
            load_stage(sb, (cc + 2) % ST, gA, Bm, K, N, n0, (cc + 2) * BK, tid);

        const int s = cc % ST;
        const uint32_t* Asu = (const uint32_t*)(smem + s * STAGE_BYTES);
        const uint32_t* Bsu = (const uint32_t*)(smem + s * STAGE_BYTES + A_ST_BYTES);

        #pragma unroll
        for (int ks = 0; ks < 2; ks++) {
            const int kb = ks * 8 + q;
            uint32_t af[4][4], bf[4][2];
            #pragma unroll
            for (int mt = 0; mt < 4; mt++) {
                const int m = wm + mt * 16 + r4;
                af[mt][0] = Asu[m * ARS + kb];
                af[mt][1] = Asu[(m + 8) * ARS + kb];
                af[mt][2] = Asu[m * ARS + kb + 4];
                af[mt][3] = Asu[(m + 8) * ARS + kb + 4];
            }
            #pragma unroll
            for (int nt = 0; nt < 4; nt++) {
                const int n = wn + nt * 8 + r4;
                bf[nt][0] = Bsu[kb * BRS + n];
                bf[nt][1] = Bsu[(kb + 4) * BRS + n];
            }
            #pragma unroll
            for (int mt = 0; mt < 4; mt++)
                #pragma unroll
                for (int nt = 0; nt < 4; nt++)
                    MMA_TF32(c[mt][nt], af[mt], bf[nt]);
        }
    }

    // epilogue: bias (+relu) (+tf32 round), float2 stores
    #pragma unroll
    for (int mt = 0; mt < 4; mt++) {
        #pragma unroll
        for (int nt = 0; nt < 4; nt++) {
            const int col = n0 + wn + nt * 8 + q * 2;
            const float2 bv = *(const float2*)(bias + col);
            #pragma unroll
            for (int hh = 0; hh < 2; hh++) {
                const int row = m0 + wm + mt * 16 + r4 + hh * 8;
                float2 o;
                o.x = c[mt][nt][hh * 2 + 0] + bv.x;
                o.y = c[mt][nt][hh * 2 + 1] + bv.y;
                if (RELU) { o.x = fmaxf(o.x, 0.f); o.y = fmaxf(o.y, 0.f); }
                if (RND)  { o.x = tf32_rn(o.x);    o.y = tf32_rn(o.y); }
                *(float2*)(C + (size_t)row * N + col) = o;
            }
        }
    }
}

// ---------------------------------------------------------------------------
// round_copy: out[i] = tf32(in[i])  (vectorized)
// ---------------------------------------------------------------------------
__global__ __launch_bounds__(256)
void round_copy(const float* __restrict__ in, float* __restrict__ out, int n4) {
    int i = blockIdx.x * 256 + threadIdx.x;
    if (i < n4) {
        float4 v = ((const float4*)in)[i];
        v.x = tf32_rn(v.x); v.y = tf32_rn(v.y);
        v.z = tf32_rn(v.z); v.w = tf32_rn(v.w);
        ((float4*)out)[i] = v;
    }
}

// ---------------------------------------------------------------------------
// QK^T / sqrt(d), output rounded to tf32 (feeds tf32 MMA)
// ---------------------------------------------------------------------------
__global__ __launch_bounds__(256)
void qk_kernel(const float* __restrict__ Q, const float* __restrict__ Km,
               float* __restrict__ S) {
    __shared__ float Qs[64][65];
    __shared__ float Ks[64][65];
    const int b  = blockIdx.z;
    const int q0 = blockIdx.y * 64;
    const int k0 = blockIdx.x * 64;
    const int tid = threadIdx.x;

    const float* Qb = Q  + ((size_t)b * S_ + q0) * D_;
    const float* Kb = Km + ((size_t)b * S_ + k0) * D_;

    #pragma unroll
    for (int i = tid; i < 64 * 16; i += 256) {
        int r = i >> 4;
        int c = (i & 15) * 4;
        float4 v = *(const float4*)(Qb + (size_t)r * D_ + c);
        Qs[r][c] = v.x; Qs[r][c + 1] = v.y; Qs[r][c + 2] = v.z; Qs[r][c + 3] = v.w;
        float4 w = *(const float4*)(Kb + (size_t)r * D_ + c);
        Ks[r][c] = w.x; Ks[r][c + 1] = w.y; Ks[r][c + 2] = w.z; Ks[r][c + 3] = w.w;
    }
    __syncthreads();

    const int tx = tid & 15;
    const int ty = tid >> 4;
    float acc[4][4] = {};
    #pragma unroll 8
    for (int d = 0; d < 64; d++) {
        float a[4], bb[4];
        #pragma unroll
        for (int i = 0; i < 4; i++) a[i]  = Qs[ty * 4 + i][d];
        #pragma unroll
        for (int j = 0; j < 4; j++) bb[j] = Ks[tx * 4 + j][d];
        #pragma unroll
        for (int i = 0; i < 4; i++)
            #pragma unroll
            for (int j = 0; j < 4; j++)
                acc[i][j] = fmaf(a[i], bb[j], acc[i][j]);
    }

    #pragma unroll
    for (int i = 0; i < 4; i++) {
        float4 o;
        o.x = tf32_rn(acc[i][0] * 0.125f);
        o.y = tf32_rn(acc[i][1] * 0.125f);
        o.z = tf32_rn(acc[i][2] * 0.125f);
        o.w = tf32_rn(acc[i][3] * 0.125f);
        *(float4*)(S + ((size_t)b * S_ + q0 + ty * 4 + i) * S_ + k0 + tx * 4) = o;
    }
}

// ---------------------------------------------------------------------------
// Row softmax over S_=2048, in place
// ---------------------------------------------------------------------------
__global__ __launch_bounds__(256)
void softmax_kernel(float* __restrict__ X) {
    __shared__ float red[8];
    float* x = X + (size_t)blockIdx.x * S_;
    const int tid = threadIdx.x;
    const int wid = tid >> 5, lane = tid & 31;

    float4 v0 = ((const float4*)x)[tid];
    float4 v1 = ((const float4*)x)[tid + 256];

    float m = fmaxf(fmaxf(fmaxf(v0.x, v0.y), fmaxf(v0.z, v0.w)),
                    fmaxf(fmaxf(v1.x, v1.y), fmaxf(v1.z, v1.w)));
    #pragma unroll
    for (int o = 16; o > 0; o >>= 1) m = fmaxf(m, __shfl_xor_sync(0xffffffffu, m, o));
    if (lane == 0) red[wid] = m;
    __syncthreads();
    if (tid < 32) {
        float t = (tid < 8) ? red[tid] : -INFINITY;
        #pragma unroll
        for (int o = 4; o > 0; o >>= 1) t = fmaxf(t, __shfl_xor_sync(0xffffffffu, t, o));
        if (tid == 0) red[0] = t;
    }
    __syncthreads();
    m = red[0];
    __syncthreads();

    v0.x = __expf(v0.x - m); v0.y = __expf(v0.y - m);
    v0.z = __expf(v0.z - m); v0.w = __expf(v0.w - m);
    v1.x = __expf(v1.x - m); v1.y = __expf(v1.y - m);
    v1.z = __expf(v1.z - m); v1.w = __expf(v1.w - m);
    float s = (v0.x + v0.y + v0.z + v0.w) + (v1.x + v1.y + v1.z + v1.w);
    #pragma unroll
    for (int o = 16; o > 0; o >>= 1) s += __shfl_xor_sync(0xffffffffu, s, o);
    if (lane == 0) red[wid] = s;
    __syncthreads();
    if (tid < 32) {
        float t = (tid < 8) ? red[tid] : 0.f;
        #pragma unroll
        for (int o = 4; o > 0; o >>= 1) t += __shfl_xor_sync(0xffffffffu, t, o);
        if (tid == 0) red[0] = t;
    }
    __syncthreads();
    const float inv = 1.0f / red[0];

    v0.x *= inv; v0.y *= inv; v0.z *= inv; v0.w *= inv;
    v1.x *= inv; v1.y *= inv; v1.z *= inv; v1.w *= inv;
    ((float4*)x)[tid] = v0;
    ((float4*)x)[tid + 256] = v1;
}

// ---------------------------------------------------------------------------
// out[b,q,:] = attn[b,q,:] @ V[b,:,:]
// ---------------------------------------------------------------------------
__global__ __launch_bounds__(256)
void av_kernel(const float* __restrict__ attn, const float* __restrict__ V,
               float* __restrict__ out) {
    const int b    = blockIdx.y;
    const int q    = blockIdx.x * 4 + (threadIdx.x >> 6);
    const int lane = threadIdx.x & 63;

    const float* arow = attn + ((size_t)b * S_ + q) * S_;
    const float* Vb   = V + (size_t)b * S_ * D_ + lane;

    float acc = 0.f;
    #pragma unroll 4
    for (int k = 0; k < S_; k += 4) {
        float4 s = *(const float4*)(arow + k);
        acc = fmaf(s.x, Vb[(size_t)(k + 0) * D_], acc);
        acc = fmaf(s.y, Vb[(size_t)(k + 1) * D_], acc);
        acc = fmaf(s.z, Vb[(size_t)(k + 2) * D_], acc);
        acc = fmaf(s.w, Vb[(size_t)(k + 3) * D_], acc);
    }
    out[((size_t)b * S_ + q) * D_ + lane] = acc;
}

// ---------------------------------------------------------------------------
// Launch
// ---------------------------------------------------------------------------
extern "C" void kernel_launch(void* const* d_in, const int* in_sizes, int n_in,
                              void* d_out, int out_size) {
    const float* Q  = (const float*)d_in[0];
    const float* K  = (const float*)d_in[1];
    const float* V  = (const float*)d_in[2];
    const float* W1 = (const float*)d_in[3];
    const float* b1 = (const float*)d_in[4];
    const float* W2 = (const float*)d_in[5];
    const float* b2 = (const float*)d_in[6];
    float* out = (float*)d_out;

    float *scores, *h, *w1r, *w2r;
    cudaGetSymbolAddress((void**)&scores, g_scores);
    cudaGetSymbolAddress((void**)&h, g_h);
    cudaGetSymbolAddress((void**)&w1r, g_w1r);
    cudaGetSymbolAddress((void**)&w2r, g_w2r);

    cudaFuncSetAttribute(mma_gemm<true, true>,
                         cudaFuncAttributeMaxDynamicSharedMemorySize, GEMM_SMEM);
    cudaFuncSetAttribute(mma_gemm<false, false>,
                         cudaFuncAttributeMaxDynamicSharedMemorySize, GEMM_SMEM);

    // 0) tf32-rounded weights (unbiased RN; MMA truncation then exact)
    const int nW = S_ * H_ / 4;
    round_copy<<<(nW + 255) / 256, 256>>>(W1, w1r, nW);
    round_copy<<<(nW + 255) / 256, 256>>>(W2, w2r, nW);

    // 1) scores = tf32(Q K^T / sqrt(d))
    qk_kernel<<<dim3(S_ / 64, S_ / 64, B_), 256>>>(Q, K, scores);

    // 2) h = tf32(relu(scores @ W1 + b1))   [tensor core tf32]
    mma_gemm<true, true><<<dim3(H_ / BN, S_ / BM, B_), 256, GEMM_SMEM>>>(
        scores, w1r, b1, h, S_, H_, S_);

    // 3) logits = h @ W2 + b2 -> scores buffer   [tensor core tf32]
    mma_gemm<false, false><<<dim3(S_ / BN, S_ / BM, B_), 256, GEMM_SMEM>>>(
        h, w2r, b2, scores, S_, S_, H_);

    // 4) softmax rows (in place)
    softmax_kernel<<<B_ * S_, 256>>>(scores);

    // 5) out = attn @ V
    av_kernel<<<dim3(S_ / 4, B_), 256>>>(scores, V, out);
}

// round 7
// speedup vs baseline: 4.9170x; 1.6534x over previous
#include <cuda_runtime.h>
#include <math.h>
#include <stdint.h>

#define B_  8
#define S_  2048
#define D_  64
#define H_  4096

// Scratch (__device__ globals: the sanctioned alloc-free path)
__device__ float g_scores[(size_t)B_ * S_ * S_];   // 128 MB (adjusted -> attn)
__device__ float g_h[(size_t)B_ * S_ * H_];        // 256 MB
__device__ float g_w1r[(size_t)S_ * H_];           // 32 MB  tf32 W1 [K,N]
__device__ float g_w2r[(size_t)H_ * S_];           // 32 MB  tf32 W2 [K,N]
__device__ float g_kt [(size_t)B_ * D_ * S_];      // 4 MB   tf32 K^T stacked [512, 2048]
__device__ float g_kw1[(size_t)B_ * D_ * H_];      // 8 MB   tf32 (K^T W1)/8 stacked [512, 4096]
__device__ float g_qr [(size_t)B_ * S_ * D_];      // 4 MB   tf32 Q

// ---------------------------------------------------------------------------
// helpers
// ---------------------------------------------------------------------------
__device__ __forceinline__ float tf32_rn(float x) {
    float r; asm("cvt.rna.tf32.f32 %0, %1;" : "=f"(r) : "f"(x)); return r;
}
__device__ __forceinline__ void cp16(uint32_t dst, const void* src) {
    asm volatile("cp.async.cg.shared.global [%0], [%1], 16;" :: "r"(dst), "l"(src) : "memory");
}
#define CP_COMMIT() asm volatile("cp.async.commit_group;" ::: "memory")
#define CP_WAIT1()  asm volatile("cp.async.wait_group 1;" ::: "memory")
#define CP_WAIT0()  asm volatile("cp.async.wait_group 0;" ::: "memory")

__device__ __forceinline__ uint32_t smem_u32(const void* p) {
    uint32_t a;
    asm("{ .reg .u64 t; cvta.to.shared.u64 t, %1; cvt.u32.u64 %0, t; }" : "=r"(a) : "l"(p));
    return a;
}

#define MMA_TF32(c, a, b)                                                      \
    asm volatile(                                                              \
        "mma.sync.aligned.m16n8k8.row.col.f32.tf32.tf32.f32 "                  \
        "{%0,%1,%2,%3}, {%4,%5,%6,%7}, {%8,%9}, {%0,%1,%2,%3};"                \
        : "+f"((c)[0]), "+f"((c)[1]), "+f"((c)[2]), "+f"((c)[3])               \
        : "r"((a)[0]), "r"((a)[1]), "r"((a)[2]), "r"((a)[3]),                  \
          "r"((b)[0]), "r"((b)[1]))

// ---------------------------------------------------------------------------
// tf32 mma.sync GEMM:  C[z] = act(scale * (A[z] @ B[z]) + bias)
// A: [M,K] row-major, batch stride M*K. B: [K,N] row-major, batch stride bStride.
// CTA tile 128x128, BK=16, 3-stage cp.async, 8 warps (2x4), warp tile 64x32.
// 2 CTAs/SM (reg-capped); one barrier per k-chunk.
// ---------------------------------------------------------------------------
constexpr int BM = 128, BN = 128, BK = 16, ST = 3;
constexpr int ARS = 20;    // A smem row stride (floats)
constexpr int BRS = 136;   // B smem row stride (floats)
constexpr int A_ST_BYTES = BM * ARS * 4;                  // 10240
constexpr int B_ST_BYTES = BK * BRS * 4;                  // 8704
constexpr int STAGE_BYTES = A_ST_BYTES + B_ST_BYTES;      // 18944
constexpr int GEMM_SMEM = ST * STAGE_BYTES;               // 56832

__device__ __forceinline__ void load_stage(uint32_t sb, int s, const float* gA,
                                           const float* gB, int K, int N,
                                           int n0, int k0, int tid) {
    const uint32_t aB = sb + s * STAGE_BYTES;
    const uint32_t bB = aB + A_ST_BYTES;
    // A: 128 rows x 4 chunks of 16B
    #pragma unroll
    for (int i = 0; i < 2; i++) {
        int t = i * 256 + tid;
        int r = t >> 2, c = t & 3;
        cp16(aB + (uint32_t)(r * ARS + c * 4) * 4, gA + (size_t)r * K + k0 + c * 4);
    }
    // B: 16 rows x 32 chunks of 16B
    #pragma unroll
    for (int i = 0; i < 2; i++) {
        int t = i * 256 + tid;
        int r = t >> 5, c = t & 31;
        cp16(bB + (uint32_t)(r * BRS + c * 4) * 4, gB + (size_t)(k0 + r) * N + n0 + c * 4);
    }
    CP_COMMIT();
}

template <bool RELU, bool RND, bool BIAS>
__global__ __launch_bounds__(256, 2)
void mma_gemm(const float* __restrict__ A, const float* __restrict__ Bm,
              const float* __restrict__ bias, float* __restrict__ C,
              int M, int N, int K, float scale, size_t bStride) {
    extern __shared__ char smem[];
    const uint32_t sb = smem_u32(smem);
    const int tid = threadIdx.x;
    const int w = tid >> 5, L = tid & 31;
    const int wm = (w >> 2) * 64;          // warp row offset in tile
    const int wn = (w & 3) * 32;           // warp col offset in tile
    const int q = L & 3, r4 = L >> 2;

    const int m0 = blockIdx.y * BM, n0 = blockIdx.x * BN;
    A  += (size_t)blockIdx.z * M * K;
    Bm += (size_t)blockIdx.z * bStride;
    C  += (size_t)blockIdx.z * M * N;
    const float* gA = A + (size_t)m0 * K;
    const int NC = K / BK;

    float c[4][4][4] = {};   // [mt][nt][frag]

    load_stage(sb, 0, gA, Bm, K, N, n0, 0, tid);
    load_stage(sb, 1, gA, Bm, K, N, n0, BK, tid);

    for (int cc = 0; cc < NC; cc++) {
        if (cc == NC - 1) { CP_WAIT0(); } else { CP_WAIT1(); }
        __syncthreads();
        // Load targets stage (cc+2)%3 == (cc-1)%3, already consumed by all
        // warps before the barrier above — one barrier per chunk suffices.
        if (cc + 2 < NC)
            load_stage(sb, (cc + 2) % ST, gA, Bm, K, N, n0, (cc + 2) * BK, tid);

        const int s = cc % ST;
        const uint32_t* Asu = (const uint32_t*)(smem + s * STAGE_BYTES);
        const uint32_t* Bsu = (const uint32_t*)(smem + s * STAGE_BYTES + A_ST_BYTES);

        #pragma unroll
        for (int ks = 0; ks < 2; ks++) {
            const int kb = ks * 8 + q;
            uint32_t af[4][4], bf[4][2];
            #pragma unroll
            for (int mt = 0; mt < 4; mt++) {
                const int m = wm + mt * 16 + r4;
                af[mt][0] = Asu[m * ARS + kb];
                af[mt][1] = Asu[(m + 8) * ARS + kb];
                af[mt][2] = Asu[m * ARS + kb + 4];
                af[mt][3] = Asu[(m + 8) * ARS + kb + 4];
            }
            #pragma unroll
            for (int nt = 0; nt < 4; nt++) {
                const int n = wn + nt * 8 + r4;
                bf[nt][0] = Bsu[kb * BRS + n];
                bf[nt][1] = Bsu[(kb + 4) * BRS + n];
            }
            #pragma unroll
            for (int mt = 0; mt < 4; mt++)
                #pragma unroll
                for (int nt = 0; nt < 4; nt++)
                    MMA_TF32(c[mt][nt], af[mt], bf[nt]);
        }
    }

    // epilogue: scale, bias (+relu) (+tf32 round), float2 stores
    #pragma unroll
    for (int mt = 0; mt < 4; mt++) {
        #pragma unroll
        for (int nt = 0; nt < 4; nt++) {
            const int col = n0 + wn + nt * 8 + q * 2;
            float2 bv = BIAS ? *(const float2*)(bias + col) : make_float2(0.f, 0.f);
            #pragma unroll
            for (int hh = 0; hh < 2; hh++) {
                const int row = m0 + wm + mt * 16 + r4 + hh * 8;
                float2 o;
                o.x = c[mt][nt][hh * 2 + 0] * scale + bv.x;
                o.y = c[mt][nt][hh * 2 + 1] * scale + bv.y;
                if (RELU) { o.x = fmaxf(o.x, 0.f); o.y = fmaxf(o.y, 0.f); }
                if (RND)  { o.x = tf32_rn(o.x);    o.y = tf32_rn(o.y); }
                *(float2*)(C + (size_t)row * N + col) = o;
            }
        }
    }
}

// ---------------------------------------------------------------------------
// round_copy: out[i] = tf32(in[i])  (vectorized)
// ---------------------------------------------------------------------------
__global__ __launch_bounds__(256)
void round_copy(const float* __restrict__ in, float* __restrict__ out, int n4) {
    int i = blockIdx.x * 256 + threadIdx.x;
    if (i < n4) {
        float4 v = ((const float4*)in)[i];
        v.x = tf32_rn(v.x); v.y = tf32_rn(v.y);
        v.z = tf32_rn(v.z); v.w = tf32_rn(v.w);
        ((float4*)out)[i] = v;
    }
}

// ---------------------------------------------------------------------------
// transpose_k: Kt[z*64 + d][s] = tf32(K[z][s][d])   (stacked across batches)
// ---------------------------------------------------------------------------
__global__ __launch_bounds__(256)
void transpose_k(const float* __restrict__ Kin, float* __restrict__ Kt) {
    __shared__ float t[32][33];
    const int z = blockIdx.z;
    const int s0 = blockIdx.x * 32, d0 = blockIdx.y * 32;
    const float* Kb = Kin + (size_t)z * S_ * D_;
    #pragma unroll
    for (int i = 0; i < 4; i++)
        t[threadIdx.y + i * 8][threadIdx.x] =
            Kb[(size_t)(s0 + threadIdx.y + i * 8) * D_ + d0 + threadIdx.x];
    __syncthreads();
    float* Ob = Kt + (size_t)z * D_ * S_;
    #pragma unroll
    for (int i = 0; i < 4; i++)
        Ob[(size_t)(d0 + threadIdx.y + i * 8) * S_ + s0 + threadIdx.x] =
            tf32_rn(t[threadIdx.x][threadIdx.y + i * 8]);
}

// ---------------------------------------------------------------------------
// Row softmax over S_=2048, in place
// ---------------------------------------------------------------------------
__global__ __launch_bounds__(256)
void softmax_kernel(float* __restrict__ X) {
    __shared__ float red[8];
    float* x = X + (size_t)blockIdx.x * S_;
    const int tid = threadIdx.x;
    const int wid = tid >> 5, lane = tid & 31;

    float4 v0 = ((const float4*)x)[tid];
    float4 v1 = ((const float4*)x)[tid + 256];

    float m = fmaxf(fmaxf(fmaxf(v0.x, v0.y), fmaxf(v0.z, v0.w)),
                    fmaxf(fmaxf(v1.x, v1.y), fmaxf(v1.z, v1.w)));
    #pragma unroll
    for (int o = 16; o > 0; o >>= 1) m = fmaxf(m, __shfl_xor_sync(0xffffffffu, m, o));
    if (lane == 0) red[wid] = m;
    __syncthreads();
    if (tid < 32) {
        float t = (tid < 8) ? red[tid] : -INFINITY;
        #pragma unroll
        for (int o = 4; o > 0; o >>= 1) t = fmaxf(t, __shfl_xor_sync(0xffffffffu, t, o));
        if (tid == 0) red[0] = t;
    }
    __syncthreads();
    m = red[0];
    __syncthreads();

    v0.x = __expf(v0.x - m); v0.y = __expf(v0.y - m);
    v0.z = __expf(v0.z - m); v0.w = __expf(v0.w - m);
    v1.x = __expf(v1.x - m); v1.y = __expf(v1.y - m);
    v1.z = __expf(v1.z - m); v1.w = __expf(v1.w - m);
    float s = (v0.x + v0.y + v0.z + v0.w) + (v1.x + v1.y + v1.z + v1.w);
    #pragma unroll
    for (int o = 16; o > 0; o >>= 1) s += __shfl_xor_sync(0xffffffffu, s, o);
    if (lane == 0) red[wid] = s;
    __syncthreads();
    if (tid < 32) {
        float t = (tid < 8) ? red[tid] : 0.f;
        #pragma unroll
        for (int o = 4; o > 0; o >>= 1) t += __shfl_xor_sync(0xffffffffu, t, o);
        if (tid == 0) red[0] = t;
    }
    __syncthreads();
    const float inv = 1.0f / red[0];

    v0.x *= inv; v0.y *= inv; v0.z *= inv; v0.w *= inv;
    v1.x *= inv; v1.y *= inv; v1.z *= inv; v1.w *= inv;
    ((float4*)x)[tid] = v0;
    ((float4*)x)[tid + 256] = v1;
}

// ---------------------------------------------------------------------------
// out[b,q,:] = attn[b,q,:] @ V[b,:,:]
// ---------------------------------------------------------------------------
__global__ __launch_bounds__(256)
void av_kernel(const float* __restrict__ attn, const float* __restrict__ V,
               float* __restrict__ out) {
    const int b    = blockIdx.y;
    const int q    = blockIdx.x * 4 + (threadIdx.x >> 6);
    const int lane = threadIdx.x & 63;

    const float* arow = attn + ((size_t)b * S_ + q) * S_;
    const float* Vb   = V + (size_t)b * S_ * D_ + lane;

    float acc = 0.f;
    #pragma unroll 4
    for (int k = 0; k < S_; k += 4) {
        float4 s = *(const float4*)(arow + k);
        acc = fmaf(s.x, Vb[(size_t)(k + 0) * D_], acc);
        acc = fmaf(s.y, Vb[(size_t)(k + 1) * D_], acc);
        acc = fmaf(s.z, Vb[(size_t)(k + 2) * D_], acc);
        acc = fmaf(s.w, Vb[(size_t)(k + 3) * D_], acc);
    }
    out[((size_t)b * S_ + q) * D_ + lane] = acc;
}

// ---------------------------------------------------------------------------
// Launch
// ---------------------------------------------------------------------------
extern "C" void kernel_launch(void* const* d_in, const int* in_sizes, int n_in,
                              void* d_out, int out_size) {
    const float* Q  = (const float*)d_in[0];
    const float* K  = (const float*)d_in[1];
    const float* V  = (const float*)d_in[2];
    const float* W1 = (const float*)d_in[3];
    const float* b1 = (const float*)d_in[4];
    const float* W2 = (const float*)d_in[5];
    const float* b2 = (const float*)d_in[6];
    float* out = (float*)d_out;

    float *scores, *h, *w1r, *w2r, *kt, *kw1, *qr;
    cudaGetSymbolAddress((void**)&scores, g_scores);
    cudaGetSymbolAddress((void**)&h, g_h);
    cudaGetSymbolAddress((void**)&w1r, g_w1r);
    cudaGetSymbolAddress((void**)&w2r, g_w2r);
    cudaGetSymbolAddress((void**)&kt, g_kt);
    cudaGetSymbolAddress((void**)&kw1, g_kw1);
    cudaGetSymbolAddress((void**)&qr, g_qr);

    cudaFuncSetAttribute(mma_gemm<false, true, false>,
                         cudaFuncAttributeMaxDynamicSharedMemorySize, GEMM_SMEM);
    cudaFuncSetAttribute(mma_gemm<true, true, true>,
                         cudaFuncAttributeMaxDynamicSharedMemorySize, GEMM_SMEM);
    cudaFuncSetAttribute(mma_gemm<false, false, true>,
                         cudaFuncAttributeMaxDynamicSharedMemorySize, GEMM_SMEM);

    // 0) tf32-rounded operands
    const int nW = S_ * H_ / 4;
    round_copy<<<(nW + 255) / 256, 256>>>(W1, w1r, nW);
    round_copy<<<(nW + 255) / 256, 256>>>(W2, w2r, nW);
    const int nQ = B_ * S_ * D_ / 4;
    round_copy<<<(nQ + 255) / 256, 256>>>(Q, qr, nQ);
    transpose_k<<<dim3(S_ / 32, D_ / 32, B_), dim3(32, 8)>>>(K, kt);

    // 1) KW1 = tf32((K^T @ W1) / 8)  — all batches stacked: [512,2048]x[2048,4096]
    mma_gemm<false, true, false><<<dim3(H_ / BN, (B_ * D_) / BM, 1), 256, GEMM_SMEM>>>(
        kt, w1r, nullptr, kw1, B_ * D_, H_, S_, 0.125f, 0);

    // 2) h = tf32(relu(Q @ KW1 + b1))  — thin K=64 GEMM, per batch
    mma_gemm<true, true, true><<<dim3(H_ / BN, S_ / BM, B_), 256, GEMM_SMEM>>>(
        qr, kw1, b1, h, S_, H_, D_, 1.0f, (size_t)D_ * H_);

    // 3) adjusted = h @ W2 + b2 -> scores buffer  (dominant GEMM)
    mma_gemm<false, false, true><<<dim3(S_ / BN, S_ / BM, B_), 256, GEMM_SMEM>>>(
        h, w2r, b2, scores, S_, S_, H_, 1.0f, 0);

    // 4) softmax rows (in place)
    softmax_kernel<<<B_ * S_, 256>>>(scores);

    // 5) out = attn @ V
    av_kernel<<<dim3(S_ / 4, B_), 256>>>(scores, V, out);
}

// round 8
// speedup vs baseline: 5.0532x; 1.0277x over previous
#include <cuda_runtime.h>
#include <math.h>
#include <stdint.h>

#define B_  8
#define S_  2048
#define D_  64
#define H_  4096

// Scratch (__device__ globals: the sanctioned alloc-free path)
__device__ float g_scores[(size_t)B_ * S_ * S_];   // 128 MB (adjusted -> attn)
__device__ float g_h[(size_t)B_ * S_ * H_];        // 256 MB
__device__ float g_w1r[(size_t)S_ * H_];           // 32 MB  tf32 W1 [K,N]
__device__ float g_w2r[(size_t)H_ * S_];           // 32 MB  tf32 W2 [K,N]
__device__ float g_kt [(size_t)B_ * D_ * S_];      // 4 MB   tf32 K^T stacked [512, 2048]
__device__ float g_kw1[(size_t)B_ * D_ * H_];      // 8 MB   tf32 (K^T W1)/8 stacked [512, 4096]
__device__ float g_qr [(size_t)B_ * S_ * D_];      // 4 MB   tf32 Q

// ---------------------------------------------------------------------------
// helpers
// ---------------------------------------------------------------------------
__device__ __forceinline__ float tf32_rn(float x) {
    float r; asm("cvt.rna.tf32.f32 %0, %1;" : "=f"(r) : "f"(x)); return r;
}
__device__ __forceinline__ void cp16(uint32_t dst, const void* src) {
    asm volatile("cp.async.cg.shared.global [%0], [%1], 16;" :: "r"(dst), "l"(src) : "memory");
}
#define CP_COMMIT() asm volatile("cp.async.commit_group;" ::: "memory")
#define CP_WAIT1()  asm volatile("cp.async.wait_group 1;" ::: "memory")
#define CP_WAIT0()  asm volatile("cp.async.wait_group 0;" ::: "memory")

__device__ __forceinline__ uint32_t smem_u32(const void* p) {
    uint32_t a;
    asm("{ .reg .u64 t; cvta.to.shared.u64 t, %1; cvt.u32.u64 %0, t; }" : "=r"(a) : "l"(p));
    return a;
}

#define MMA_TF32(c, a, b)                                                      \
    asm volatile(                                                              \
        "mma.sync.aligned.m16n8k8.row.col.f32.tf32.tf32.f32 "                  \
        "{%0,%1,%2,%3}, {%4,%5,%6,%7}, {%8,%9}, {%0,%1,%2,%3};"                \
        : "+f"((c)[0]), "+f"((c)[1]), "+f"((c)[2]), "+f"((c)[3])               \
        : "r"((a)[0]), "r"((a)[1]), "r"((a)[2]), "r"((a)[3]),                  \
          "r"((b)[0]), "r"((b)[1]))

// ---------------------------------------------------------------------------
// tf32 mma.sync GEMM:  C[z] = act(scale * (A[z] @ B[z]) + bias)
// A: [M,K] row-major, batch stride M*K. B: [K,N] row-major, batch stride bStride.
// CTA tile 128x128, BK=32 (4 k-steps per barrier), 3-stage cp.async,
// 8 warps (2x4), warp tile 64x32, 2 CTAs/SM (128-reg cap).
// ---------------------------------------------------------------------------
constexpr int BM = 128, BN = 128, BK = 32, ST = 3;
constexpr int ARS = 36;    // A smem row stride (floats): 32 k + pad4
constexpr int BRS = 136;   // B smem row stride (floats): 128 n + pad8
constexpr int A_ST_BYTES = BM * ARS * 4;                  // 18432
constexpr int B_ST_BYTES = BK * BRS * 4;                  // 17408
constexpr int STAGE_BYTES = A_ST_BYTES + B_ST_BYTES;      // 35840
constexpr int GEMM_SMEM = ST * STAGE_BYTES;               // 107520

__device__ __forceinline__ void load_stage(uint32_t sb, int s, const float* gA,
                                           const float* gB, int K, int N,
                                           int n0, int k0, int tid) {
    const uint32_t aB = sb + s * STAGE_BYTES;
    const uint32_t bB = aB + A_ST_BYTES;
    // A: 128 rows x 8 chunks of 16B  (1024 cp16, 4 per thread)
    #pragma unroll
    for (int i = 0; i < 4; i++) {
        int t = i * 256 + tid;
        int r = t >> 3, c = t & 7;
        cp16(aB + (uint32_t)(r * ARS + c * 4) * 4, gA + (size_t)r * K + k0 + c * 4);
    }
    // B: 32 rows x 32 chunks of 16B  (1024 cp16, 4 per thread)
    #pragma unroll
    for (int i = 0; i < 4; i++) {
        int t = i * 256 + tid;
        int r = t >> 5, c = t & 31;
        cp16(bB + (uint32_t)(r * BRS + c * 4) * 4, gB + (size_t)(k0 + r) * N + n0 + c * 4);
    }
    CP_COMMIT();
}

template <bool RELU, bool RND, bool BIAS>
__global__ __launch_bounds__(256, 2)
void mma_gemm(const float* __restrict__ A, const float* __restrict__ Bm,
              const float* __restrict__ bias, float* __restrict__ C,
              int M, int N, int K, float scale, size_t bStride) {
    extern __shared__ char smem[];
    const uint32_t sb = smem_u32(smem);
    const int tid = threadIdx.x;
    const int w = tid >> 5, L = tid & 31;
    const int wm = (w >> 2) * 64;          // warp row offset in tile
    const int wn = (w & 3) * 32;           // warp col offset in tile
    const int q = L & 3, r4 = L >> 2;

    const int m0 = blockIdx.y * BM, n0 = blockIdx.x * BN;
    A  += (size_t)blockIdx.z * M * K;
    Bm += (size_t)blockIdx.z * bStride;
    C  += (size_t)blockIdx.z * M * N;
    const float* gA = A + (size_t)m0 * K;
    const int NC = K / BK;

    float c[4][4][4] = {};   // [mt][nt][frag]

    load_stage(sb, 0, gA, Bm, K, N, n0, 0, tid);
    load_stage(sb, 1, gA, Bm, K, N, n0, BK, tid);

    for (int cc = 0; cc < NC; cc++) {
        if (cc == NC - 1) { CP_WAIT0(); } else { CP_WAIT1(); }
        __syncthreads();
        // Load targets stage (cc+2)%3 == (cc-1)%3, already consumed by all
        // warps before the barrier above — one barrier per chunk suffices.
        if (cc + 2 < NC)
            load_stage(sb, (cc + 2) % ST, gA, Bm, K, N, n0, (cc + 2) * BK, tid);

        const int s = cc % ST;
        const uint32_t* Asu = (const uint32_t*)(smem + s * STAGE_BYTES);
        const uint32_t* Bsu = (const uint32_t*)(smem + s * STAGE_BYTES + A_ST_BYTES);

        #pragma unroll
        for (int ks = 0; ks < 4; ks++) {
            const int kb = ks * 8 + q;
            uint32_t af[4][4], bf[4][2];
            #pragma unroll
            for (int mt = 0; mt < 4; mt++) {
                const int m = wm + mt * 16 + r4;
                af[mt][0] = Asu[m * ARS + kb];
                af[mt][1] = Asu[(m + 8) * ARS + kb];
                af[mt][2] = Asu[m * ARS + kb + 4];
                af[mt][3] = Asu[(m + 8) * ARS + kb + 4];
            }
            #pragma unroll
            for (int nt = 0; nt < 4; nt++) {
                const int n = wn + nt * 8 + r4;
                bf[nt][0] = Bsu[kb * BRS + n];
                bf[nt][1] = Bsu[(kb + 4) * BRS + n];
            }
            #pragma unroll
            for (int mt = 0; mt < 4; mt++)
                #pragma unroll
                for (int nt = 0; nt < 4; nt++)
                    MMA_TF32(c[mt][nt], af[mt], bf[nt]);
        }
    }

    // epilogue: scale, bias (+relu) (+tf32 round), float2 stores
    #pragma unroll
    for (int mt = 0; mt < 4; mt++) {
        #pragma unroll
        for (int nt = 0; nt < 4; nt++) {
            const int col = n0 + wn + nt * 8 + q * 2;
            float2 bv = BIAS ? *(const float2*)(bias + col) : make_float2(0.f, 0.f);
            #pragma unroll
            for (int hh = 0; hh < 2; hh++) {
                const int row = m0 + wm + mt * 16 + r4 + hh * 8;
                float2 o;
                o.x = c[mt][nt][hh * 2 + 0] * scale + bv.x;
                o.y = c[mt][nt][hh * 2 + 1] * scale + bv.y;
                if (RELU) { o.x = fmaxf(o.x, 0.f); o.y = fmaxf(o.y, 0.f); }
                if (RND)  { o.x = tf32_rn(o.x);    o.y = tf32_rn(o.y); }
                *(float2*)(C + (size_t)row * N + col) = o;
            }
        }
    }
}

// ---------------------------------------------------------------------------
// round_copy: out[i] = tf32(in[i])  (vectorized)
// ---------------------------------------------------------------------------
__global__ __launch_bounds__(256)
void round_copy(const float* __restrict__ in, float* __restrict__ out, int n4) {
    int i = blockIdx.x * 256 + threadIdx.x;
    if (i < n4) {
        float4 v = ((const float4*)in)[i];
        v.x = tf32_rn(v.x); v.y = tf32_rn(v.y);
        v.z = tf32_rn(v.z); v.w = tf32_rn(v.w);
        ((float4*)out)[i] = v;
    }
}

// ---------------------------------------------------------------------------
// transpose_k: Kt[z*64 + d][s] = tf32(K[z][s][d])   (stacked across batches)
// ---------------------------------------------------------------------------
__global__ __launch_bounds__(256)
void transpose_k(const float* __restrict__ Kin, float* __restrict__ Kt) {
    __shared__ float t[32][33];
    const int z = blockIdx.z;
    const int s0 = blockIdx.x * 32, d0 = blockIdx.y * 32;
    const float* Kb = Kin + (size_t)z * S_ * D_;
    #pragma unroll
    for (int i = 0; i < 4; i++)
        t[threadIdx.y + i * 8][threadIdx.x] =
            Kb[(size_t)(s0 + threadIdx.y + i * 8) * D_ + d0 + threadIdx.x];
    __syncthreads();
    float* Ob = Kt + (size_t)z * D_ * S_;
    #pragma unroll
    for (int i = 0; i < 4; i++)
        Ob[(size_t)(d0 + threadIdx.y + i * 8) * S_ + s0 + threadIdx.x] =
            tf32_rn(t[threadIdx.x][threadIdx.y + i * 8]);
}

// ---------------------------------------------------------------------------
// Row softmax over S_=2048, in place
// ---------------------------------------------------------------------------
__global__ __launch_bounds__(256)
void softmax_kernel(float* __restrict__ X) {
    __shared__ float red[8];
    float* x = X + (size_t)blockIdx.x * S_;
    const int tid = threadIdx.x;
    const int wid = tid >> 5, lane = tid & 31;

    float4 v0 = ((const float4*)x)[tid];
    float4 v1 = ((const float4*)x)[tid + 256];

    float m = fmaxf(fmaxf(fmaxf(v0.x, v0.y), fmaxf(v0.z, v0.w)),
                    fmaxf(fmaxf(v1.x, v1.y), fmaxf(v1.z, v1.w)));
    #pragma unroll
    for (int o = 16; o > 0; o >>= 1) m = fmaxf(m, __shfl_xor_sync(0xffffffffu, m, o));
    if (lane == 0) red[wid] = m;
    __syncthreads();
    if (tid < 32) {
        float t = (tid < 8) ? red[tid] : -INFINITY;
        #pragma unroll
        for (int o = 4; o > 0; o >>= 1) t = fmaxf(t, __shfl_xor_sync(0xffffffffu, t, o));
        if (tid == 0) red[0] = t;
    }
    __syncthreads();
    m = red[0];
    __syncthreads();

    v0.x = __expf(v0.x - m); v0.y = __expf(v0.y - m);
    v0.z = __expf(v0.z - m); v0.w = __expf(v0.w - m);
    v1.x = __expf(v1.x - m); v1.y = __expf(v1.y - m);
    v1.z = __expf(v1.z - m); v1.w = __expf(v1.w - m);
    float s = (v0.x + v0.y + v0.z + v0.w) + (v1.x + v1.y + v1.z + v1.w);
    #pragma unroll
    for (int o = 16; o > 0; o >>= 1) s += __shfl_xor_sync(0xffffffffu, s, o);
    if (lane == 0) red[wid] = s;
    __syncthreads();
    if (tid < 32) {
        float t = (tid < 8) ? red[tid] : 0.f;
        #pragma unroll
        for (int o = 4; o > 0; o >>= 1) t += __shfl_xor_sync(0xffffffffu, t, o);
        if (tid == 0) red[0] = t;
    }
    __syncthreads();
    const float inv = 1.0f / red[0];

    v0.x *= inv; v0.y *= inv; v0.z *= inv; v0.w *= inv;
    v1.x *= inv; v1.y *= inv; v1.z *= inv; v1.w *= inv;
    ((float4*)x)[tid] = v0;
    ((float4*)x)[tid + 256] = v1;
}

// ---------------------------------------------------------------------------
// out[b,q,:] = attn[b,q,:] @ V[b,:,:]
// ---------------------------------------------------------------------------
__global__ __launch_bounds__(256)
void av_kernel(const float* __restrict__ attn, const float* __restrict__ V,
               float* __restrict__ out) {
    const int b    = blockIdx.y;
    const int q    = blockIdx.x * 4 + (threadIdx.x >> 6);
    const int lane = threadIdx.x & 63;

    const float* arow = attn + ((size_t)b * S_ + q) * S_;
    const float* Vb   = V + (size_t)b * S_ * D_ + lane;

    float acc = 0.f;
    #pragma unroll 4
    for (int k = 0; k < S_; k += 4) {
        float4 s = *(const float4*)(arow + k);
        acc = fmaf(s.x, Vb[(size_t)(k + 0) * D_], acc);
        acc = fmaf(s.y, Vb[(size_t)(k + 1) * D_], acc);
        acc = fmaf(s.z, Vb[(size_t)(k + 2) * D_], acc);
        acc = fmaf(s.w, Vb[(size_t)(k + 3) * D_], acc);
    }
    out[((size_t)b * S_ + q) * D_ + lane] = acc;
}

// ---------------------------------------------------------------------------
// Launch
// ---------------------------------------------------------------------------
extern "C" void kernel_launch(void* const* d_in, const int* in_sizes, int n_in,
                              void* d_out, int out_size) {
    const float* Q  = (const float*)d_in[0];
    const float* K  = (const float*)d_in[1];
    const float* V  = (const float*)d_in[2];
    const float* W1 = (const float*)d_in[3];
    const float* b1 = (const float*)d_in[4];
    const float* W2 = (const float*)d_in[5];
    const float* b2 = (const float*)d_in[6];
    float* out = (float*)d_out;

    float *scores, *h, *w1r, *w2r, *kt, *kw1, *qr;
    cudaGetSymbolAddress((void**)&scores, g_scores);
    cudaGetSymbolAddress((void**)&h, g_h);
    cudaGetSymbolAddress((void**)&w1r, g_w1r);
    cudaGetSymbolAddress((void**)&w2r, g_w2r);
    cudaGetSymbolAddress((void**)&kt, g_kt);
    cudaGetSymbolAddress((void**)&kw1, g_kw1);
    cudaGetSymbolAddress((void**)&qr, g_qr);

    cudaFuncSetAttribute(mma_gemm<false, true, false>,
                         cudaFuncAttributeMaxDynamicSharedMemorySize, GEMM_SMEM);
    cudaFuncSetAttribute(mma_gemm<true, true, true>,
                         cudaFuncAttributeMaxDynamicSharedMemorySize, GEMM_SMEM);
    cudaFuncSetAttribute(mma_gemm<false, false, true>,
                         cudaFuncAttributeMaxDynamicSharedMemorySize, GEMM_SMEM);

    // 0) tf32-rounded operands
    const int nW = S_ * H_ / 4;
    round_copy<<<(nW + 255) / 256, 256>>>(W1, w1r, nW);
    round_copy<<<(nW + 255) / 256, 256>>>(W2, w2r, nW);
    const int nQ = B_ * S_ * D_ / 4;
    round_copy<<<(nQ + 255) / 256, 256>>>(Q, qr, nQ);
    transpose_k<<<dim3(S_ / 32, D_ / 32, B_), dim3(32, 8)>>>(K, kt);

    // 1) KW1 = tf32((K^T @ W1) / 8)  — all batches stacked: [512,2048]x[2048,4096]
    mma_gemm<false, true, false><<<dim3(H_ / BN, (B_ * D_) / BM, 1), 256, GEMM_SMEM>>>(
        kt, w1r, nullptr, kw1, B_ * D_, H_, S_, 0.125f, 0);

    // 2) h = tf32(relu(Q @ KW1 + b1))  — thin K=64 GEMM, per batch
    mma_gemm<true, true, true><<<dim3(H_ / BN, S_ / BM, B_), 256, GEMM_SMEM>>>(
        qr, kw1, b1, h, S_, H_, D_, 1.0f, (size_t)D_ * H_);

    // 3) adjusted = h @ W2 + b2 -> scores buffer  (dominant GEMM)
    mma_gemm<false, false, true><<<dim3(S_ / BN, S_ / BM, B_), 256, GEMM_SMEM>>>(
        h, w2r, b2, scores, S_, S_, H_, 1.0f, 0);

    // 4) softmax rows (in place)
    softmax_kernel<<<B_ * S_, 256>>>(scores);

    // 5) out = attn @ V
    av_kernel<<<dim3(S_ / 4, B_), 256>>>(scores, V, out);
}

// round 11
// speedup vs baseline: 7.0507x; 1.3953x over previous
#include <cuda_runtime.h>
#include <cuda_fp16.h>
#include <math.h>
#include <stdint.h>

#define B_  8
#define S_  2048
#define D_  64
#define H_  4096

// Scratch (__device__ globals: the sanctioned alloc-free path)
__device__ float  g_scores[(size_t)B_ * S_ * S_];     // 128 MB (adjusted -> attn), fp32
__device__ __half g_h_h   [(size_t)B_ * S_ * H_];     // 128 MB  h (fp16)
__device__ __half g_w1t_h [(size_t)H_ * S_];          // 16 MB   W1^T fp16 [4096,2048]
__device__ __half g_w2t_h [(size_t)S_ * H_];          // 16 MB   W2^T fp16 [2048,4096]
__device__ __half g_kt_h  [(size_t)B_ * D_ * S_];     // 2 MB    K^T stacked fp16 [512,2048]
__device__ __half g_kw1t_h[(size_t)B_ * H_ * D_];     // 4 MB    (K^T W1 / 8)^T fp16 [b][4096][64]
__device__ __half g_q_h   [(size_t)B_ * S_ * D_];     // 2 MB    Q fp16

// ---------------------------------------------------------------------------
// helpers
// ---------------------------------------------------------------------------
__device__ __forceinline__ void cp16(uint32_t dst, const void* src) {
    asm volatile("cp.async.cg.shared.global [%0], [%1], 16;" :: "r"(dst), "l"(src) : "memory");
}
#define CP_COMMIT() asm volatile("cp.async.commit_group;" ::: "memory")
#define CP_WAIT1()  asm volatile("cp.async.wait_group 1;" ::: "memory")
#define CP_WAIT0()  asm volatile("cp.async.wait_group 0;" ::: "memory")

__device__ __forceinline__ uint32_t smem_u32(const void* p) {
    uint32_t a;
    asm("{ .reg .u64 t; cvta.to.shared.u64 t, %1; cvt.u32.u64 %0, t; }" : "=r"(a) : "l"(p));
    return a;
}

#define MMA_F16(c, a, b)                                                       \
    asm volatile(                                                              \
        "mma.sync.aligned.m16n8k16.row.col.f32.f16.f16.f32 "                   \
        "{%0,%1,%2,%3}, {%4,%5,%6,%7}, {%8,%9}, {%0,%1,%2,%3};"                \
        : "+f"((c)[0]), "+f"((c)[1]), "+f"((c)[2]), "+f"((c)[3])               \
        : "r"((a)[0]), "r"((a)[1]), "r"((a)[2]), "r"((a)[3]),                  \
          "r"((b)[0]), "r"((b)[1]))

// ---------------------------------------------------------------------------
// fp16 mma.sync GEMM:  C[z] = act(scale * (A[z] @ Bt[z]^T) + bias)
// A:  [M,K] row-major fp16, batch stride aStride.
// Bt: [N,K] row-major fp16 (i.e. B column-major), batch stride bStride.
// CTA tile 128x128, BK=32 halves (2 k16-steps), 3-stage cp.async,
// 8 warps (2x4), warp tile 64x32, 2 CTAs/SM.
// OUT: 0 = fp32 row-major, 1 = fp16 row-major, 2 = fp16 transposed for kw1t
//      (store at [(row>>6)*N + col]*64 + (row&63); used by GEMM1 only).
// ---------------------------------------------------------------------------
constexpr int BM = 128, BN = 128, BK = 32, ST = 3;
constexpr int AW = 20;                     // smem row stride in 32-bit words (16 + 4 pad)
constexpr int TILE_H_BYTES = 128 * AW * 4; // 10240 per operand
constexpr int STAGE_BYTES = 2 * TILE_H_BYTES;   // 20480
constexpr int GEMM_SMEM = ST * STAGE_BYTES;     // 61440

__device__ __forceinline__ void load_stage(uint32_t sb, int s, const __half* gA,
                                           const __half* gB, int K, int k0, int tid) {
    const uint32_t aB = sb + s * STAGE_BYTES;
    const uint32_t bB = aB + TILE_H_BYTES;
    // A tile: 128 rows x 4 chunks of 16B (8 halves)
    #pragma unroll
    for (int i = 0; i < 2; i++) {
        int t = i * 256 + tid;
        int r = t >> 2, c = t & 3;
        cp16(aB + (uint32_t)(r * AW + c * 4) * 4, gA + (size_t)r * K + k0 + c * 8);
    }
    // B tile (Bt rows): 128 rows x 4 chunks of 16B
    #pragma unroll
    for (int i = 0; i < 2; i++) {
        int t = i * 256 + tid;
        int r = t >> 2, c = t & 3;
        cp16(bB + (uint32_t)(r * AW + c * 4) * 4, gB + (size_t)r * K + k0 + c * 8);
    }
    CP_COMMIT();
}

template <int OUT, bool RELU, bool BIAS>
__global__ __launch_bounds__(256, 2)
void mma_gemm_h(const __half* __restrict__ A, const __half* __restrict__ Bt,
                const float* __restrict__ bias, void* __restrict__ Cv,
                int M, int N, int K, float scale,
                size_t aStride, size_t bStride, size_t cStride) {
    extern __shared__ char smem[];
    const uint32_t sb = smem_u32(smem);
    const int tid = threadIdx.x;
    const int w = tid >> 5, L = tid & 31;
    const int wm = (w >> 2) * 64;          // warp row offset in tile
    const int wn = (w & 3) * 32;           // warp col offset in tile
    const int q = L & 3, r4 = L >> 2;

    const int m0 = blockIdx.y * BM, n0 = blockIdx.x * BN;
    A  += (size_t)blockIdx.z * aStride;
    Bt += (size_t)blockIdx.z * bStride;
    const __half* gA = A + (size_t)m0 * K;
    const __half* gB = Bt + (size_t)n0 * K;
    const int NC = K / BK;

    float c[4][4][4] = {};   // [mt][nt][frag]

    load_stage(sb, 0, gA, gB, K, 0, tid);
    load_stage(sb, 1, gA, gB, K, BK, tid);

    for (int cc = 0; cc < NC; cc++) {
        if (cc == NC - 1) { CP_WAIT0(); } else { CP_WAIT1(); }
        __syncthreads();
        // Load targets stage (cc+2)%3 == (cc-1)%3, consumed by all warps
        // before the barrier above — one barrier per chunk suffices.
        if (cc + 2 < NC)
            load_stage(sb, (cc + 2) % ST, gA, gB, K, (cc + 2) * BK, tid);

        const int s = cc % ST;
        const uint32_t* Asu = (const uint32_t*)(smem + s * STAGE_BYTES);
        const uint32_t* Bsu = (const uint32_t*)(smem + s * STAGE_BYTES + TILE_H_BYTES);

        #pragma unroll
        for (int ks = 0; ks < 2; ks++) {       // two k16 steps per BK=32 chunk
            uint32_t af[4][4], bf[4][2];
            #pragma unroll
            for (int mt = 0; mt < 4; mt++) {
                const int m = wm + mt * 16 + r4;
                af[mt][0] = Asu[m * AW + ks * 8 + q];
                af[mt][1] = Asu[(m + 8) * AW + ks * 8 + q];
                af[mt][2] = Asu[m * AW + ks * 8 + 4 + q];
                af[mt][3] = Asu[(m + 8) * AW + ks * 8 + 4 + q];
            }
            #pragma unroll
            for (int nt = 0; nt < 4; nt++) {
                const int n = wn + nt * 8 + r4;
                bf[nt][0] = Bsu[n * AW + ks * 8 + q];
                bf[nt][1] = Bsu[n * AW + ks * 8 + 4 + q];
            }
            #pragma unroll
            for (int mt = 0; mt < 4; mt++)
                #pragma unroll
                for (int nt = 0; nt < 4; nt++)
                    MMA_F16(c[mt][nt], af[mt], bf[nt]);
        }
    }

    // epilogue
    #pragma unroll
    for (int mt = 0; mt < 4; mt++) {
        #pragma unroll
        for (int nt = 0; nt < 4; nt++) {
            const int col = n0 + wn + nt * 8 + q * 2;
            float2 bv = BIAS ? *(const float2*)(bias + col) : make_float2(0.f, 0.f);
            #pragma unroll
            for (int hh = 0; hh < 2; hh++) {
                const int row = m0 + wm + mt * 16 + r4 + hh * 8;
                float ox = c[mt][nt][hh * 2 + 0] * scale + bv.x;
                float oy = c[mt][nt][hh * 2 + 1] * scale + bv.y;
                if (RELU) { ox = fmaxf(ox, 0.f); oy = fmaxf(oy, 0.f); }
                if (OUT == 0) {
                    float* C = (float*)Cv + (size_t)blockIdx.z * cStride;
                    *(float2*)(C + (size_t)row * N + col) = make_float2(ox, oy);
                } else if (OUT == 1) {
                    __half* C = (__half*)Cv + (size_t)blockIdx.z * cStride;
                    *(__half2*)(C + (size_t)row * N + col) =
                        __floats2half2_rn(ox, oy);
                } else {
                    // transposed fp16 store: kw1t[(row/64)][col][row%64]
                    __half* C = (__half*)Cv;
                    const size_t base = ((size_t)(row >> 6) * N) * 64 + (row & 63);
                    C[base + (size_t)col * 64]       = __float2half_rn(ox);
                    C[base + (size_t)(col + 1) * 64] = __float2half_rn(oy);
                }
            }
        }
    }
}

// ---------------------------------------------------------------------------
// transpose_h: out[c][r] = fp16(in[r][c]) per batch; in [R,C] fp32.
// ---------------------------------------------------------------------------
__global__ __launch_bounds__(256)
void transpose_h(const float* __restrict__ in, __half* __restrict__ out,
                 int R, int C, size_t inStride, size_t outStride) {
    __shared__ float t[32][33];
    const int z = blockIdx.z;
    const int c0 = blockIdx.x * 32, r0 = blockIdx.y * 32;
    const float* ib = in + (size_t)z * inStride;
    #pragma unroll
    for (int i = 0; i < 4; i++)
        t[threadIdx.y + i * 8][threadIdx.x] =
            ib[(size_t)(r0 + threadIdx.y + i * 8) * C + c0 + threadIdx.x];
    __syncthreads();
    __half* ob = out + (size_t)z * outStride;
    #pragma unroll
    for (int i = 0; i < 4; i++)
        ob[(size_t)(c0 + threadIdx.y + i * 8) * R + r0 + threadIdx.x] =
            __float2half_rn(t[threadIdx.x][threadIdx.y + i * 8]);
}

// ---------------------------------------------------------------------------
// conv_h: fp32 -> fp16 elementwise (vectorized 4-wide)
// ---------------------------------------------------------------------------
__global__ __launch_bounds__(256)
void conv_h(const float* __restrict__ in, __half* __restrict__ out, int n4) {
    int i = blockIdx.x * 256 + threadIdx.x;
    if (i < n4) {
        float4 v = ((const float4*)in)[i];
        __half2 a = __floats2half2_rn(v.x, v.y);
        __half2 b = __floats2half2_rn(v.z, v.w);
        *(uint32_t*)&((__half*)out)[i * 4]     = *(uint32_t*)&a;
        *(uint32_t*)&((__half*)out)[i * 4 + 2] = *(uint32_t*)&b;
    }
}

// ---------------------------------------------------------------------------
// Row softmax over S_=2048, in place (fp32)
// ---------------------------------------------------------------------------
__global__ __launch_bounds__(256)
void softmax_kernel(float* __restrict__ X) {
    __shared__ float red[8];
    float* x = X + (size_t)blockIdx.x * S_;
    const int tid = threadIdx.x;
    const int wid = tid >> 5, lane = tid & 31;

    float4 v0 = ((const float4*)x)[tid];
    float4 v1 = ((const float4*)x)[tid + 256];

    float m = fmaxf(fmaxf(fmaxf(v0.x, v0.y), fmaxf(v0.z, v0.w)),
                    fmaxf(fmaxf(v1.x, v1.y), fmaxf(v1.z, v1.w)));
    #pragma unroll
    for (int o = 16; o > 0; o >>= 1) m = fmaxf(m, __shfl_xor_sync(0xffffffffu, m, o));
    if (lane == 0) red[wid] = m;
    __syncthreads();
    if (tid < 32) {
        float t = (tid < 8) ? red[tid] : -INFINITY;
        #pragma unroll
        for (int o = 4; o > 0; o >>= 1) t = fmaxf(t, __shfl_xor_sync(0xffffffffu, t, o));
        if (tid == 0) red[0] = t;
    }
    __syncthreads();
    m = red[0];
    __syncthreads();

    v0.x = __expf(v0.x - m); v0.y = __expf(v0.y - m);
    v0.z = __expf(v0.z - m); v0.w = __expf(v0.w - m);
    v1.x = __expf(v1.x - m); v1.y = __expf(v1.y - m);
    v1.z = __expf(v1.z - m); v1.w = __expf(v1.w - m);
    float s = (v0.x + v0.y + v0.z + v0.w) + (v1.x + v1.y + v1.z + v1.w);
    #pragma unroll
    for (int o = 16; o > 0; o >>= 1) s += __shfl_xor_sync(0xffffffffu, s, o);
    if (lane == 0) red[wid] = s;
    __syncthreads();
    if (tid < 32) {
        float t = (tid < 8) ? red[tid] : 0.f;
        #pragma unroll
        for (int o = 4; o > 0; o >>= 1) t += __shfl_xor_sync(0xffffffffu, t, o);
        if (tid == 0) red[0] = t;
    }
    __syncthreads();
    const float inv = 1.0f / red[0];

    v0.x *= inv; v0.y *= inv; v0.z *= inv; v0.w *= inv;
    v1.x *= inv; v1.y *= inv; v1.z *= inv; v1.w *= inv;
    ((float4*)x)[tid] = v0;
    ((float4*)x)[tid + 256] = v1;
}

// ---------------------------------------------------------------------------
// out[b,q,:] = attn[b,q,:] @ V[b,:,:]   (fp32)
// ---------------------------------------------------------------------------
__global__ __launch_bounds__(256)
void av_kernel(const float* __restrict__ attn, const float* __restrict__ V,
               float* __restrict__ out) {
    const int b    = blockIdx.y;
    const int q    = blockIdx.x * 4 + (threadIdx.x >> 6);
    const int lane = threadIdx.x & 63;

    const float* arow = attn + ((size_t)b * S_ + q) * S_;
    const float* Vb   = V + (size_t)b * S_ * D_ + lane;

    float acc = 0.f;
    #pragma unroll 4
    for (int k = 0; k < S_; k += 4) {
        float4 s = *(const float4*)(arow + k);
        acc = fmaf(s.x, Vb[(size_t)(k + 0) * D_], acc);
        acc = fmaf(s.y, Vb[(size_t)(k + 1) * D_], acc);
        acc = fmaf(s.z, Vb[(size_t)(k + 2) * D_], acc);
        acc = fmaf(s.w, Vb[(size_t)(k + 3) * D_], acc);
    }
    out[((size_t)b * S_ + q) * D_ + lane] = acc;
}

// ---------------------------------------------------------------------------
// Launch
// ---------------------------------------------------------------------------
extern "C" void kernel_launch(void* const* d_in, const int* in_sizes, int n_in,
                              void* d_out, int out_size) {
    const float* Q  = (const float*)d_in[0];
    const float* K  = (const float*)d_in[1];
    const float* V  = (const float*)d_in[2];
    const float* W1 = (const float*)d_in[3];
    const float* b1 = (const float*)d_in[4];
    const float* W2 = (const float*)d_in[5];
    const float* b2 = (const float*)d_in[6];
    float* out = (float*)d_out;

    float *scores;
    __half *hh, *w1t, *w2t, *kt, *kw1t, *qh;
    cudaGetSymbolAddress((void**)&scores, g_scores);
    cudaGetSymbolAddress((void**)&hh, g_h_h);
    cudaGetSymbolAddress((void**)&w1t, g_w1t_h);
    cudaGetSymbolAddress((void**)&w2t, g_w2t_h);
    cudaGetSymbolAddress((void**)&kt, g_kt_h);
    cudaGetSymbolAddress((void**)&kw1t, g_kw1t_h);
    cudaGetSymbolAddress((void**)&qh, g_q_h);

    cudaFuncSetAttribute(mma_gemm_h<2, false, false>,
                         cudaFuncAttributeMaxDynamicSharedMemorySize, GEMM_SMEM);
    cudaFuncSetAttribute(mma_gemm_h<1, true, true>,
                         cudaFuncAttributeMaxDynamicSharedMemorySize, GEMM_SMEM);
    cudaFuncSetAttribute(mma_gemm_h<0, false, true>,
                         cudaFuncAttributeMaxDynamicSharedMemorySize, GEMM_SMEM);

    // 0) fp16 operands
    //    W1^T: [2048,4096] -> [4096,2048];  W2^T: [4096,2048] -> [2048,4096]
    transpose_h<<<dim3(H_ / 32, S_ / 32, 1), dim3(32, 8)>>>(W1, w1t, S_, H_, 0, 0);
    transpose_h<<<dim3(S_ / 32, H_ / 32, 1), dim3(32, 8)>>>(W2, w2t, H_, S_, 0, 0);
    //    K^T stacked: per batch [2048,64] -> [64,2048]
    transpose_h<<<dim3(D_ / 32, S_ / 32, B_), dim3(32, 8)>>>(
        K, kt, S_, D_, (size_t)S_ * D_, (size_t)D_ * S_);
    //    Q fp16
    conv_h<<<(B_ * S_ * D_ / 4 + 255) / 256, 256>>>(Q, qh, B_ * S_ * D_ / 4);

    // 1) kw1t = fp16((K^T @ W1)/8), stored transposed per batch [4096,64]
    //    A = kt [512,2048], Bt = W1^T [4096,2048]
    mma_gemm_h<2, false, false><<<dim3(H_ / BN, (B_ * D_) / BM, 1), 256, GEMM_SMEM>>>(
        kt, w1t, nullptr, kw1t, B_ * D_, H_, S_, 0.125f, 0, 0, 0);

    // 2) h = fp16(relu(Q @ KW1 + b1)) per batch; Bt = kw1t [4096,64]
    mma_gemm_h<1, true, true><<<dim3(H_ / BN, S_ / BM, B_), 256, GEMM_SMEM>>>(
        qh, kw1t, b1, hh, S_, H_, D_, 1.0f,
        (size_t)S_ * D_, (size_t)H_ * D_, (size_t)S_ * H_);

    // 3) adjusted = h @ W2 + b2 -> scores (fp32); Bt = W2^T [2048,4096]
    mma_gemm_h<0, false, true><<<dim3(S_ / BN, S_ / BM, B_), 256, GEMM_SMEM>>>(
        hh, w2t, b2, scores, S_, S_, H_, 1.0f,
        (size_t)S_ * H_, 0, (size_t)S_ * S_);

    // 4) softmax rows (in place)
    softmax_kernel<<<B_ * S_, 256>>>(scores);

    // 5) out = attn @ V
    av_kernel<<<dim3(S_ / 4, B_), 256>>>(scores, V, out);
}

// round 12
// speedup vs baseline: 7.7745x; 1.1027x over previous
#include <cuda_runtime.h>
#include <cuda_fp16.h>
#include <math.h>
#include <stdint.h>

#define B_  8
#define S_  2048
#define D_  64
#define H_  4096

// Scratch (__device__ globals: the sanctioned alloc-free path)
__device__ float  g_scores[(size_t)B_ * S_ * S_];     // 128 MB (adjusted -> attn), fp32
__device__ __half g_h_h   [(size_t)B_ * S_ * H_];     // 128 MB  h (fp16)
__device__ __half g_w1t_h [(size_t)H_ * S_];          // 16 MB   W1^T fp16 [4096,2048]
__device__ __half g_w2t_h [(size_t)S_ * H_];          // 16 MB   W2^T fp16 [2048,4096]
__device__ __half g_kt_h  [(size_t)B_ * D_ * S_];     // 2 MB    K^T stacked fp16 [512,2048]
__device__ __half g_kw1t_h[(size_t)B_ * H_ * D_];     // 4 MB    (K^T W1 / 8)^T fp16 [b][4096][64]
__device__ __half g_q_h   [(size_t)B_ * S_ * D_];     // 2 MB    Q fp16

// ---------------------------------------------------------------------------
// helpers
// ---------------------------------------------------------------------------
__device__ __forceinline__ void cp16(uint32_t dst, const void* src) {
    asm volatile("cp.async.cg.shared.global [%0], [%1], 16;" :: "r"(dst), "l"(src) : "memory");
}
#define CP_COMMIT() asm volatile("cp.async.commit_group;" ::: "memory")
#define CP_WAIT1()  asm volatile("cp.async.wait_group 1;" ::: "memory")
#define CP_WAIT0()  asm volatile("cp.async.wait_group 0;" ::: "memory")

__device__ __forceinline__ uint32_t smem_u32(const void* p) {
    uint32_t a;
    asm("{ .reg .u64 t; cvta.to.shared.u64 t, %1; cvt.u32.u64 %0, t; }" : "=r"(a) : "l"(p));
    return a;
}

#define MMA_F16(c, a, b)                                                       \
    asm volatile(                                                              \
        "mma.sync.aligned.m16n8k16.row.col.f32.f16.f16.f32 "                   \
        "{%0,%1,%2,%3}, {%4,%5,%6,%7}, {%8,%9}, {%0,%1,%2,%3};"                \
        : "+f"((c)[0]), "+f"((c)[1]), "+f"((c)[2]), "+f"((c)[3])               \
        : "r"((a)[0]), "r"((a)[1]), "r"((a)[2]), "r"((a)[3]),                  \
          "r"((b)[0]), "r"((b)[1]))

#define LDSM4(r0, r1, r2, r3, addr)                                            \
    asm volatile("ldmatrix.sync.aligned.m8n8.x4.shared.b16 {%0,%1,%2,%3}, [%4];"\
        : "=r"(r0), "=r"(r1), "=r"(r2), "=r"(r3) : "r"(addr))

// ---------------------------------------------------------------------------
// fp16 mma.sync GEMM:  C[z] = act(scale * (A[z] @ Bt[z]^T) + bias)
// A:  [M,K] row-major fp16, batch stride aStride.
// Bt: [N,K] row-major fp16 (i.e. B column-major), batch stride bStride.
// CTA tile 128x128, BK=32 halves (2 k16-steps), 3-stage cp.async,
// 8 warps (2x4), warp tile 64x32, 2 CTAs/SM. Fragments via ldmatrix.x4.
// OUT: 0 = fp32 row-major, 1 = fp16 row-major, 2 = fp16 transposed for kw1t.
// ---------------------------------------------------------------------------
constexpr int BM = 128, BN = 128, BK = 32, ST = 3;
constexpr int AW = 20;                     // smem row stride in 32-bit words (16 + 4 pad)
constexpr int TILE_H_BYTES = 128 * AW * 4; // 10240 per operand
constexpr int STAGE_BYTES = 2 * TILE_H_BYTES;   // 20480
constexpr int GEMM_SMEM = ST * STAGE_BYTES;     // 61440

__device__ __forceinline__ void load_stage(uint32_t sb, int s, const __half* gA,
                                           const __half* gB, int K, int k0, int tid) {
    const uint32_t aB = sb + s * STAGE_BYTES;
    const uint32_t bB = aB + TILE_H_BYTES;
    // A tile: 128 rows x 4 chunks of 16B (8 halves)
    #pragma unroll
    for (int i = 0; i < 2; i++) {
        int t = i * 256 + tid;
        int r = t >> 2, c = t & 3;
        cp16(aB + (uint32_t)(r * AW + c * 4) * 4, gA + (size_t)r * K + k0 + c * 8);
    }
    // B tile (Bt rows): 128 rows x 4 chunks of 16B
    #pragma unroll
    for (int i = 0; i < 2; i++) {
        int t = i * 256 + tid;
        int r = t >> 2, c = t & 3;
        cp16(bB + (uint32_t)(r * AW + c * 4) * 4, gB + (size_t)r * K + k0 + c * 8);
    }
    CP_COMMIT();
}

template <int OUT, bool RELU, bool BIAS>
__global__ __launch_bounds__(256, 2)
void mma_gemm_h(const __half* __restrict__ A, const __half* __restrict__ Bt,
                const float* __restrict__ bias, void* __restrict__ Cv,
                int M, int N, int K, float scale,
                size_t aStride, size_t bStride, size_t cStride) {
    extern __shared__ char smem[];
    const uint32_t sb = smem_u32(smem);
    const int tid = threadIdx.x;
    const int w = tid >> 5, L = tid & 31;
    const int wm = (w >> 2) * 64;          // warp row offset in tile
    const int wn = (w & 3) * 32;           // warp col offset in tile
    const int q = L & 3, r4 = L >> 2;

    const int m0 = blockIdx.y * BM, n0 = blockIdx.x * BN;
    A  += (size_t)blockIdx.z * aStride;
    Bt += (size_t)blockIdx.z * bStride;
    const __half* gA = A + (size_t)m0 * K;
    const __half* gB = Bt + (size_t)n0 * K;
    const int NC = K / BK;

    // ldmatrix per-lane address components (word units within a stage).
    // A (per mt, ks): matrices (m0k0, m8k0, m0k8, m8k8):
    //   row = wm + mt*16 + (L&7) + ((L>>3)&1)*8,  wordOff = ((L>>4)&1)*4 + ks*8
    const int aRowL  = wm + (L & 7) + ((L >> 3) & 1) * 8;
    const int aWordL = ((L >> 4) & 1) * 4;
    // B (per nt-pair p, ks): matrices (nt_a k0, nt_a k8, nt_b k0, nt_b k8):
    //   row = wn + p*16 + ((L>>4)&1)*8 + (L&7),   wordOff = ((L>>3)&1)*4 + ks*8
    const int bRowL  = wn + ((L >> 4) & 1) * 8 + (L & 7);
    const int bWordL = ((L >> 3) & 1) * 4;

    float c[4][4][4] = {};   // [mt][nt][frag]

    load_stage(sb, 0, gA, gB, K, 0, tid);
    load_stage(sb, 1, gA, gB, K, BK, tid);

    for (int cc = 0; cc < NC; cc++) {
        if (cc == NC - 1) { CP_WAIT0(); } else { CP_WAIT1(); }
        __syncthreads();
        // Load targets stage (cc+2)%3 == (cc-1)%3, consumed by all warps
        // before the barrier above — one barrier per chunk suffices.
        if (cc + 2 < NC)
            load_stage(sb, (cc + 2) % ST, gA, gB, K, (cc + 2) * BK, tid);

        const int s = cc % ST;
        const uint32_t aBase = sb + s * STAGE_BYTES;
        const uint32_t bBase = aBase + TILE_H_BYTES;

        #pragma unroll
        for (int ks = 0; ks < 2; ks++) {       // two k16 steps per BK=32 chunk
            uint32_t af[4][4], bf[4][2];
            #pragma unroll
            for (int mt = 0; mt < 4; mt++) {
                const uint32_t addr =
                    aBase + (uint32_t)((aRowL + mt * 16) * AW + aWordL + ks * 8) * 4;
                LDSM4(af[mt][0], af[mt][1], af[mt][2], af[mt][3], addr);
            }
            #pragma unroll
            for (int p = 0; p < 2; p++) {      // nt pairs (0,1) and (2,3)
                const uint32_t addr =
                    bBase + (uint32_t)((bRowL + p * 16) * AW + bWordL + ks * 8) * 4;
                LDSM4(bf[p * 2][0], bf[p * 2][1], bf[p * 2 + 1][0], bf[p * 2 + 1][1], addr);
            }
            #pragma unroll
            for (int mt = 0; mt < 4; mt++)
                #pragma unroll
                for (int nt = 0; nt < 4; nt++)
                    MMA_F16(c[mt][nt], af[mt], bf[nt]);
        }
    }

    // epilogue
    #pragma unroll
    for (int mt = 0; mt < 4; mt++) {
        #pragma unroll
        for (int nt = 0; nt < 4; nt++) {
            const int col = n0 + wn + nt * 8 + q * 2;
            float2 bv = BIAS ? *(const float2*)(bias + col) : make_float2(0.f, 0.f);
            #pragma unroll
            for (int hh = 0; hh < 2; hh++) {
                const int row = m0 + wm + mt * 16 + r4 + hh * 8;
                float ox = c[mt][nt][hh * 2 + 0] * scale + bv.x;
                float oy = c[mt][nt][hh * 2 + 1] * scale + bv.y;
                if (RELU) { ox = fmaxf(ox, 0.f); oy = fmaxf(oy, 0.f); }
                if (OUT == 0) {
                    float* C = (float*)Cv + (size_t)blockIdx.z * cStride;
                    *(float2*)(C + (size_t)row * N + col) = make_float2(ox, oy);
                } else if (OUT == 1) {
                    __half* C = (__half*)Cv + (size_t)blockIdx.z * cStride;
                    *(__half2*)(C + (size_t)row * N + col) =
                        __floats2half2_rn(ox, oy);
                } else {
                    // transposed fp16 store: kw1t[(row/64)][col][row%64]
                    __half* C = (__half*)Cv;
                    const size_t base = ((size_t)(row >> 6) * N) * 64 + (row & 63);
                    C[base + (size_t)col * 64]       = __float2half_rn(ox);
                    C[base + (size_t)(col + 1) * 64] = __float2half_rn(oy);
                }
            }
        }
    }
}

// ---------------------------------------------------------------------------
// transpose_h: out[c][r] = fp16(in[r][c]) per batch; in [R,C] fp32.
// ---------------------------------------------------------------------------
__global__ __launch_bounds__(256)
void transpose_h(const float* __restrict__ in, __half* __restrict__ out,
                 int R, int C, size_t inStride, size_t outStride) {
    __shared__ float t[32][33];
    const int z = blockIdx.z;
    const int c0 = blockIdx.x * 32, r0 = blockIdx.y * 32;
    const float* ib = in + (size_t)z * inStride;
    #pragma unroll
    for (int i = 0; i < 4; i++)
        t[threadIdx.y + i * 8][threadIdx.x] =
            ib[(size_t)(r0 + threadIdx.y + i * 8) * C + c0 + threadIdx.x];
    __syncthreads();
    __half* ob = out + (size_t)z * outStride;
    #pragma unroll
    for (int i = 0; i < 4; i++)
        ob[(size_t)(c0 + threadIdx.y + i * 8) * R + r0 + threadIdx.x] =
            __float2half_rn(t[threadIdx.x][threadIdx.y + i * 8]);
}

// ---------------------------------------------------------------------------
// conv_h: fp32 -> fp16 elementwise (vectorized 4-wide)
// ---------------------------------------------------------------------------
__global__ __launch_bounds__(256)
void conv_h(const float* __restrict__ in, __half* __restrict__ out, int n4) {
    int i = blockIdx.x * 256 + threadIdx.x;
    if (i < n4) {
        float4 v = ((const float4*)in)[i];
        __half2 a = __floats2half2_rn(v.x, v.y);
        __half2 b = __floats2half2_rn(v.z, v.w);
        *(uint32_t*)&((__half*)out)[i * 4]     = *(uint32_t*)&a;
        *(uint32_t*)&((__half*)out)[i * 4 + 2] = *(uint32_t*)&b;
    }
}

// ---------------------------------------------------------------------------
// Row softmax over S_=2048, in place (fp32)
// ---------------------------------------------------------------------------
__global__ __launch_bounds__(256)
void softmax_kernel(float* __restrict__ X) {
    __shared__ float red[8];
    float* x = X + (size_t)blockIdx.x * S_;
    const int tid = threadIdx.x;
    const int wid = tid >> 5, lane = tid & 31;

    float4 v0 = ((const float4*)x)[tid];
    float4 v1 = ((const float4*)x)[tid + 256];

    float m = fmaxf(fmaxf(fmaxf(v0.x, v0.y), fmaxf(v0.z, v0.w)),
                    fmaxf(fmaxf(v1.x, v1.y), fmaxf(v1.z, v1.w)));
    #pragma unroll
    for (int o = 16; o > 0; o >>= 1) m = fmaxf(m, __shfl_xor_sync(0xffffffffu, m, o));
    if (lane == 0) red[wid] = m;
    __syncthreads();
    if (tid < 32) {
        float t = (tid < 8) ? red[tid] : -INFINITY;
        #pragma unroll
        for (int o = 4; o > 0; o >>= 1) t = fmaxf(t, __shfl_xor_sync(0xffffffffu, t, o));
        if (tid == 0) red[0] = t;
    }
    __syncthreads();
    m = red[0];
    __syncthreads();

    v0.x = __expf(v0.x - m); v0.y = __expf(v0.y - m);
    v0.z = __expf(v0.z - m); v0.w = __expf(v0.w - m);
    v1.x = __expf(v1.x - m); v1.y = __expf(v1.y - m);
    v1.z = __expf(v1.z - m); v1.w = __expf(v1.w - m);
    float s = (v0.x + v0.y + v0.z + v0.w) + (v1.x + v1.y + v1.z + v1.w);
    #pragma unroll
    for (int o = 16; o > 0; o >>= 1) s += __shfl_xor_sync(0xffffffffu, s, o);
    if (lane == 0) red[wid] = s;
    __syncthreads();
    if (tid < 32) {
        float t = (tid < 8) ? red[tid] : 0.f;
        #pragma unroll
        for (int o = 4; o > 0; o >>= 1) t += __shfl_xor_sync(0xffffffffu, t, o);
        if (tid == 0) red[0] = t;
    }
    __syncthreads();
    const float inv = 1.0f / red[0];

    v0.x *= inv; v0.y *= inv; v0.z *= inv; v0.w *= inv;
    v1.x *= inv; v1.y *= inv; v1.z *= inv; v1.w *= inv;
    ((float4*)x)[tid] = v0;
    ((float4*)x)[tid + 256] = v1;
}

// ---------------------------------------------------------------------------
// out[b,q,:] = attn[b,q,:] @ V[b,:,:]   (fp32)
// ---------------------------------------------------------------------------
__global__ __launch_bounds__(256)
void av_kernel(const float* __restrict__ attn, const float* __restrict__ V,
               float* __restrict__ out) {
    const int b    = blockIdx.y;
    const int q    = blockIdx.x * 4 + (threadIdx.x >> 6);
    const int lane = threadIdx.x & 63;

    const float* arow = attn + ((size_t)b * S_ + q) * S_;
    const float* Vb   = V + (size_t)b * S_ * D_ + lane;

    float acc = 0.f;
    #pragma unroll 4
    for (int k = 0; k < S_; k += 4) {
        float4 s = *(const float4*)(arow + k);
        acc = fmaf(s.x, Vb[(size_t)(k + 0) * D_], acc);
        acc = fmaf(s.y, Vb[(size_t)(k + 1) * D_], acc);
        acc = fmaf(s.z, Vb[(size_t)(k + 2) * D_], acc);
        acc = fmaf(s.w, Vb[(size_t)(k + 3) * D_], acc);
    }
    out[((size_t)b * S_ + q) * D_ + lane] = acc;
}

// ---------------------------------------------------------------------------
// Launch
// ---------------------------------------------------------------------------
extern "C" void kernel_launch(void* const* d_in, const int* in_sizes, int n_in,
                              void* d_out, int out_size) {
    const float* Q  = (const float*)d_in[0];
    const float* K  = (const float*)d_in[1];
    const float* V  = (const float*)d_in[2];
    const float* W1 = (const float*)d_in[3];
    const float* b1 = (const float*)d_in[4];
    const float* W2 = (const float*)d_in[5];
    const float* b2 = (const float*)d_in[6];
    float* out = (float*)d_out;

    float *scores;
    __half *hh, *w1t, *w2t, *kt, *kw1t, *qh;
    cudaGetSymbolAddress((void**)&scores, g_scores);
    cudaGetSymbolAddress((void**)&hh, g_h_h);
    cudaGetSymbolAddress((void**)&w1t, g_w1t_h);
    cudaGetSymbolAddress((void**)&w2t, g_w2t_h);
    cudaGetSymbolAddress((void**)&kt, g_kt_h);
    cudaGetSymbolAddress((void**)&kw1t, g_kw1t_h);
    cudaGetSymbolAddress((void**)&qh, g_q_h);

    cudaFuncSetAttribute(mma_gemm_h<2, false, false>,
                         cudaFuncAttributeMaxDynamicSharedMemorySize, GEMM_SMEM);
    cudaFuncSetAttribute(mma_gemm_h<1, true, true>,
                         cudaFuncAttributeMaxDynamicSharedMemorySize, GEMM_SMEM);
    cudaFuncSetAttribute(mma_gemm_h<0, false, true>,
                         cudaFuncAttributeMaxDynamicSharedMemorySize, GEMM_SMEM);

    // 0) fp16 operands
    transpose_h<<<dim3(H_ / 32, S_ / 32, 1), dim3(32, 8)>>>(W1, w1t, S_, H_, 0, 0);
    transpose_h<<<dim3(S_ / 32, H_ / 32, 1), dim3(32, 8)>>>(W2, w2t, H_, S_, 0, 0);
    transpose_h<<<dim3(D_ / 32, S_ / 32, B_), dim3(32, 8)>>>(
        K, kt, S_, D_, (size_t)S_ * D_, (size_t)D_ * S_);
    conv_h<<<(B_ * S_ * D_ / 4 + 255) / 256, 256>>>(Q, qh, B_ * S_ * D_ / 4);

    // 1) kw1t = fp16((K^T @ W1)/8), stored transposed per batch [4096,64]
    mma_gemm_h<2, false, false><<<dim3(H_ / BN, (B_ * D_) / BM, 1), 256, GEMM_SMEM>>>(
        kt, w1t, nullptr, kw1t, B_ * D_, H_, S_, 0.125f, 0, 0, 0);

    // 2) h = fp16(relu(Q @ KW1 + b1)) per batch; Bt = kw1t [4096,64]
    mma_gemm_h<1, true, true><<<dim3(H_ / BN, S_ / BM, B_), 256, GEMM_SMEM>>>(
        qh, kw1t, b1, hh, S_, H_, D_, 1.0f,
        (size_t)S_ * D_, (size_t)H_ * D_, (size_t)S_ * H_);

    // 3) adjusted = h @ W2 + b2 -> scores (fp32); Bt = W2^T [2048,4096]
    mma_gemm_h<0, false, true><<<dim3(S_ / BN, S_ / BM, B_), 256, GEMM_SMEM>>>(
        hh, w2t, b2, scores, S_, S_, H_, 1.0f,
        (size_t)S_ * H_, 0, (size_t)S_ * S_);

    // 4) softmax rows (in place)
    softmax_kernel<<<B_ * S_, 256>>>(scores);

    // 5) out = attn @ V
    av_kernel<<<dim3(S_ / 4, B_), 256>>>(scores, V, out);
}

// round 14
// speedup vs baseline: 11.4347x; 1.4708x over previous
#include <cuda_runtime.h>
#include <cuda_fp16.h>
#include <math.h>
#include <stdint.h>

#define B_  8
#define S_  2048
#define D_  64
#define H_  4096

// Scratch (__device__ globals: the sanctioned alloc-free path)
__device__ float  g_scores[(size_t)B_ * S_ * S_];     // 128 MB (adjusted logits), fp32
__device__ __half g_h_h   [(size_t)B_ * S_ * H_];     // 128 MB  h (fp16); reused for attn fp16
__device__ __half g_w1t_h [(size_t)H_ * S_];          // 16 MB   W1^T fp16 [4096,2048]
__device__ __half g_w2t_h [(size_t)S_ * H_];          // 16 MB   W2^T fp16 [2048,4096]
__device__ __half g_kt_h  [(size_t)B_ * D_ * S_];     // 2 MB    K^T stacked fp16 [512,2048]
__device__ __half g_kw1t_h[(size_t)B_ * H_ * D_];     // 4 MB    (K^T W1 / 8)^T fp16 [b][4096][64]
__device__ __half g_q_h   [(size_t)B_ * S_ * D_];     // 2 MB    Q fp16
__device__ __half g_vt_h  [(size_t)B_ * D_ * S_];     // 2 MB    V^T fp16 [b][64][2048]

// ---------------------------------------------------------------------------
// helpers
// ---------------------------------------------------------------------------
__device__ __forceinline__ void cp16(uint32_t dst, const void* src) {
    asm volatile("cp.async.cg.shared.global [%0], [%1], 16;" :: "r"(dst), "l"(src) : "memory");
}
#define CP_COMMIT() asm volatile("cp.async.commit_group;" ::: "memory")
#define CP_WAIT1()  asm volatile("cp.async.wait_group 1;" ::: "memory")
#define CP_WAIT0()  asm volatile("cp.async.wait_group 0;" ::: "memory")

__device__ __forceinline__ uint32_t smem_u32(const void* p) {
    uint32_t a;
    asm("{ .reg .u64 t; cvta.to.shared.u64 t, %1; cvt.u32.u64 %0, t; }" : "=r"(a) : "l"(p));
    return a;
}

#define MMA_F16(c, a, b)                                                       \
    asm volatile(                                                              \
        "mma.sync.aligned.m16n8k16.row.col.f32.f16.f16.f32 "                   \
        "{%0,%1,%2,%3}, {%4,%5,%6,%7}, {%8,%9}, {%0,%1,%2,%3};"                \
        : "+f"((c)[0]), "+f"((c)[1]), "+f"((c)[2]), "+f"((c)[3])               \
        : "r"((a)[0]), "r"((a)[1]), "r"((a)[2]), "r"((a)[3]),                  \
          "r"((b)[0]), "r"((b)[1]))

#define LDSM4(r0, r1, r2, r3, addr)                                            \
    asm volatile("ldmatrix.sync.aligned.m8n8.x4.shared.b16 {%0,%1,%2,%3}, [%4];"\
        : "=r"(r0), "=r"(r1), "=r"(r2), "=r"(r3) : "r"(addr))

// ---------------------------------------------------------------------------
// fp16 mma.sync GEMM:  C[z] = act(scale * (A[z] @ Bt[z]^T) + bias)
// CTA tile 128x128, BK=32 halves, 3-stage cp.async, 8 warps (2x4),
// warp tile 64x32, 2 CTAs/SM, ldmatrix fragments.
// OUT: 0 = fp32 row-major, 1 = fp16 row-major, 2 = fp16 transposed for kw1t.
// ---------------------------------------------------------------------------
constexpr int BM = 128, BN = 128, BK = 32, ST = 3;
constexpr int AW = 20;                     // smem row stride in 32-bit words (16 + 4 pad)
constexpr int TILE_H_BYTES = 128 * AW * 4; // 10240 per operand
constexpr int STAGE_BYTES = 2 * TILE_H_BYTES;   // 20480
constexpr int GEMM_SMEM = ST * STAGE_BYTES;     // 61440

__device__ __forceinline__ void load_stage(uint32_t sb, int s, const __half* gA,
                                           const __half* gB, int K, int k0, int tid) {
    const uint32_t aB = sb + s * STAGE_BYTES;
    const uint32_t bB = aB + TILE_H_BYTES;
    #pragma unroll
    for (int i = 0; i < 2; i++) {
        int t = i * 256 + tid;
        int r = t >> 2, c = t & 3;
        cp16(aB + (uint32_t)(r * AW + c * 4) * 4, gA + (size_t)r * K + k0 + c * 8);
    }
    #pragma unroll
    for (int i = 0; i < 2; i++) {
        int t = i * 256 + tid;
        int r = t >> 2, c = t & 3;
        cp16(bB + (uint32_t)(r * AW + c * 4) * 4, gB + (size_t)r * K + k0 + c * 8);
    }
    CP_COMMIT();
}

template <int OUT, bool RELU, bool BIAS>
__global__ __launch_bounds__(256, 2)
void mma_gemm_h(const __half* __restrict__ A, const __half* __restrict__ Bt,
                const float* __restrict__ bias, void* __restrict__ Cv,
                int M, int N, int K, float scale,
                size_t aStride, size_t bStride, size_t cStride) {
    extern __shared__ char smem[];
    const uint32_t sb = smem_u32(smem);
    const int tid = threadIdx.x;
    const int w = tid >> 5, L = tid & 31;
    const int wm = (w >> 2) * 64;
    const int wn = (w & 3) * 32;
    const int q = L & 3, r4 = L >> 2;

    const int m0 = blockIdx.y * BM, n0 = blockIdx.x * BN;
    A  += (size_t)blockIdx.z * aStride;
    Bt += (size_t)blockIdx.z * bStride;
    const __half* gA = A + (size_t)m0 * K;
    const __half* gB = Bt + (size_t)n0 * K;
    const int NC = K / BK;

    const int aRowL  = wm + (L & 7) + ((L >> 3) & 1) * 8;
    const int aWordL = ((L >> 4) & 1) * 4;
    const int bRowL  = wn + ((L >> 4) & 1) * 8 + (L & 7);
    const int bWordL = ((L >> 3) & 1) * 4;

    float c[4][4][4] = {};

    load_stage(sb, 0, gA, gB, K, 0, tid);
    load_stage(sb, 1, gA, gB, K, BK, tid);

    for (int cc = 0; cc < NC; cc++) {
        if (cc == NC - 1) { CP_WAIT0(); } else { CP_WAIT1(); }
        __syncthreads();
        if (cc + 2 < NC)
            load_stage(sb, (cc + 2) % ST, gA, gB, K, (cc + 2) * BK, tid);

        const int s = cc % ST;
        const uint32_t aBase = sb + s * STAGE_BYTES;
        const uint32_t bBase = aBase + TILE_H_BYTES;

        #pragma unroll
        for (int ks = 0; ks < 2; ks++) {
            uint32_t af[4][4], bf[4][2];
            #pragma unroll
            for (int mt = 0; mt < 4; mt++) {
                const uint32_t addr =
                    aBase + (uint32_t)((aRowL + mt * 16) * AW + aWordL + ks * 8) * 4;
                LDSM4(af[mt][0], af[mt][1], af[mt][2], af[mt][3], addr);
            }
            #pragma unroll
            for (int p = 0; p < 2; p++) {
                const uint32_t addr =
                    bBase + (uint32_t)((bRowL + p * 16) * AW + bWordL + ks * 8) * 4;
                LDSM4(bf[p * 2][0], bf[p * 2][1], bf[p * 2 + 1][0], bf[p * 2 + 1][1], addr);
            }
            #pragma unroll
            for (int mt = 0; mt < 4; mt++)
                #pragma unroll
                for (int nt = 0; nt < 4; nt++)
                    MMA_F16(c[mt][nt], af[mt], bf[nt]);
        }
    }

    #pragma unroll
    for (int mt = 0; mt < 4; mt++) {
        #pragma unroll
        for (int nt = 0; nt < 4; nt++) {
            const int col = n0 + wn + nt * 8 + q * 2;
            float2 bv = BIAS ? *(const float2*)(bias + col) : make_float2(0.f, 0.f);
            #pragma unroll
            for (int hh = 0; hh < 2; hh++) {
                const int row = m0 + wm + mt * 16 + r4 + hh * 8;
                float ox = c[mt][nt][hh * 2 + 0] * scale + bv.x;
                float oy = c[mt][nt][hh * 2 + 1] * scale + bv.y;
                if (RELU) { ox = fmaxf(ox, 0.f); oy = fmaxf(oy, 0.f); }
                if (OUT == 0) {
                    float* C = (float*)Cv + (size_t)blockIdx.z * cStride;
                    *(float2*)(C + (size_t)row * N + col) = make_float2(ox, oy);
                } else if (OUT == 1) {
                    __half* C = (__half*)Cv + (size_t)blockIdx.z * cStride;
                    *(__half2*)(C + (size_t)row * N + col) =
                        __floats2half2_rn(ox, oy);
                } else {
                    __half* C = (__half*)Cv;
                    const size_t base = ((size_t)(row >> 6) * N) * 64 + (row & 63);
                    C[base + (size_t)col * 64]       = __float2half_rn(ox);
                    C[base + (size_t)(col + 1) * 64] = __float2half_rn(oy);
                }
            }
        }
    }
}

// ---------------------------------------------------------------------------
// AV tensor-core GEMM: out[z] = attn[z] @ Vt[z]^T
// attn: [2048,2048] fp16 row-major. Vt: [64,2048] fp16 (K-major).
// CTA tile 128x64, BK=32, 3-stage, 8 warps as 4(m)x2(n), warp tile 32x32.
// ---------------------------------------------------------------------------
constexpr int AV_BN = 64;
constexpr int AV_BTILE = 64 * AW * 4;                    // 5120
constexpr int AV_STAGE = TILE_H_BYTES + AV_BTILE;        // 15360
constexpr int AV_SMEM = ST * AV_STAGE;                   // 46080

__global__ __launch_bounds__(256, 2)
void av_mma(const __half* __restrict__ attn, const __half* __restrict__ Vt,
            float* __restrict__ out) {
    extern __shared__ char smem[];
    const uint32_t sb = smem_u32(smem);
    const int tid = threadIdx.x;
    const int w = tid >> 5, L = tid & 31;
    const int wm = (w >> 1) * 32;          // 4 m-groups
    const int wn = (w & 1) * 32;           // 2 n-groups
    const int q = L & 3, r4 = L >> 2;
    const int K = S_;

    const int m0 = blockIdx.y * BM;
    const int z = blockIdx.z;
    const __half* gA = attn + (size_t)z * S_ * S_ + (size_t)m0 * K;
    const __half* gB = Vt + (size_t)z * D_ * S_;
    const int NC = K / BK;                 // 64

    const int aRowL  = wm + (L & 7) + ((L >> 3) & 1) * 8;
    const int aWordL = ((L >> 4) & 1) * 4;
    const int bRowL  = wn + ((L >> 4) & 1) * 8 + (L & 7);
    const int bWordL = ((L >> 3) & 1) * 4;

    float c[2][4][4] = {};

    // stage loader (A: 128 rows, B: 64 rows)
    auto load_av = [&](int s, int k0) {
        const uint32_t aB = sb + s * AV_STAGE;
        const uint32_t bB = aB + TILE_H_BYTES;
        #pragma unroll
        for (int i = 0; i < 2; i++) {
            int t = i * 256 + tid;
            int r = t >> 2, cch = t & 3;
            cp16(aB + (uint32_t)(r * AW + cch * 4) * 4, gA + (size_t)r * K + k0 + cch * 8);
        }
        {
            int r = tid >> 2, cch = tid & 3;
            cp16(bB + (uint32_t)(r * AW + cch * 4) * 4, gB + (size_t)r * K + k0 + cch * 8);
        }
        CP_COMMIT();
    };

    load_av(0, 0);
    load_av(1, BK);

    for (int cc = 0; cc < NC; cc++) {
        if (cc == NC - 1) { CP_WAIT0(); } else { CP_WAIT1(); }
        __syncthreads();
        if (cc + 2 < NC) load_av((cc + 2) % ST, (cc + 2) * BK);

        const int s = cc % ST;
        const uint32_t aBase = sb + s * AV_STAGE;
        const uint32_t bBase = aBase + TILE_H_BYTES;

        #pragma unroll
        for (int ks = 0; ks < 2; ks++) {
            uint32_t af[2][4], bf[4][2];
            #pragma unroll
            for (int mt = 0; mt < 2; mt++) {
                const uint32_t addr =
                    aBase + (uint32_t)((aRowL + mt * 16) * AW + aWordL + ks * 8) * 4;
                LDSM4(af[mt][0], af[mt][1], af[mt][2], af[mt][3], addr);
            }
            #pragma unroll
            for (int p = 0; p < 2; p++) {
                const uint32_t addr =
                    bBase + (uint32_t)((bRowL + p * 16) * AW + bWordL + ks * 8) * 4;
                LDSM4(bf[p * 2][0], bf[p * 2][1], bf[p * 2 + 1][0], bf[p * 2 + 1][1], addr);
            }
            #pragma unroll
            for (int mt = 0; mt < 2; mt++)
                #pragma unroll
                for (int nt = 0; nt < 4; nt++)
                    MMA_F16(c[mt][nt], af[mt], bf[nt]);
        }
    }

    #pragma unroll
    for (int mt = 0; mt < 2; mt++) {
        #pragma unroll
        for (int nt = 0; nt < 4; nt++) {
            const int col = wn + nt * 8 + q * 2;
            #pragma unroll
            for (int hh = 0; hh < 2; hh++) {
                const int row = m0 + wm + mt * 16 + r4 + hh * 8;
                *(float2*)(out + ((size_t)z * S_ + row) * D_ + col) =
                    make_float2(c[mt][nt][hh * 2 + 0], c[mt][nt][hh * 2 + 1]);
            }
        }
    }
}

// ---------------------------------------------------------------------------
// transpose_h: out[c][r] = fp16(in[r][c]) per batch; in [R,C] fp32.
// ---------------------------------------------------------------------------
__global__ __launch_bounds__(256)
void transpose_h(const float* __restrict__ in, __half* __restrict__ out,
                 int R, int C, size_t inStride, size_t outStride) {
    __shared__ float t[32][33];
    const int z = blockIdx.z;
    const int c0 = blockIdx.x * 32, r0 = blockIdx.y * 32;
    const float* ib = in + (size_t)z * inStride;
    #pragma unroll
    for (int i = 0; i < 4; i++)
        t[threadIdx.y + i * 8][threadIdx.x] =
            ib[(size_t)(r0 + threadIdx.y + i * 8) * C + c0 + threadIdx.x];
    __syncthreads();
    __half* ob = out + (size_t)z * outStride;
    #pragma unroll
    for (int i = 0; i < 4; i++)
        ob[(size_t)(c0 + threadIdx.y + i * 8) * R + r0 + threadIdx.x] =
            __float2half_rn(t[threadIdx.x][threadIdx.y + i * 8]);
}

// ---------------------------------------------------------------------------
// conv_h: fp32 -> fp16 elementwise (vectorized 4-wide)
// ---------------------------------------------------------------------------
__global__ __launch_bounds__(256)
void conv_h(const float* __restrict__ in, __half* __restrict__ out, int n4) {
    int i = blockIdx.x * 256 + threadIdx.x;
    if (i < n4) {
        float4 v = ((const float4*)in)[i];
        __half2 a = __floats2half2_rn(v.x, v.y);
        __half2 b = __floats2half2_rn(v.z, v.w);
        *(uint32_t*)&((__half*)out)[i * 4]     = *(uint32_t*)&a;
        *(uint32_t*)&((__half*)out)[i * 4 + 2] = *(uint32_t*)&b;
    }
}

// ---------------------------------------------------------------------------
// Row softmax over S_=2048: read fp32 logits, write fp16 attn.
// ---------------------------------------------------------------------------
__global__ __launch_bounds__(256)
void softmax_h_kernel(const float* __restrict__ X, __half* __restrict__ Y) {
    __shared__ float red[8];
    const float* x = X + (size_t)blockIdx.x * S_;
    __half* y = Y + (size_t)blockIdx.x * S_;
    const int tid = threadIdx.x;
    const int wid = tid >> 5, lane = tid & 31;

    float4 v0 = ((const float4*)x)[tid];
    float4 v1 = ((const float4*)x)[tid + 256];

    float m = fmaxf(fmaxf(fmaxf(v0.x, v0.y), fmaxf(v0.z, v0.w)),
                    fmaxf(fmaxf(v1.x, v1.y), fmaxf(v1.z, v1.w)));
    #pragma unroll
    for (int o = 16; o > 0; o >>= 1) m = fmaxf(m, __shfl_xor_sync(0xffffffffu, m, o));
    if (lane == 0) red[wid] = m;
    __syncthreads();
    if (tid < 32) {
        float t = (tid < 8) ? red[tid] : -INFINITY;
        #pragma unroll
        for (int o = 4; o > 0; o >>= 1) t = fmaxf(t, __shfl_xor_sync(0xffffffffu, t, o));
        if (tid == 0) red[0] = t;
    }
    __syncthreads();
    m = red[0];
    __syncthreads();

    v0.x = __expf(v0.x - m); v0.y = __expf(v0.y - m);
    v0.z = __expf(v0.z - m); v0.w = __expf(v0.w - m);
    v1.x = __expf(v1.x - m); v1.y = __expf(v1.y - m);
    v1.z = __expf(v1.z - m); v1.w = __expf(v1.w - m);
    float s = (v0.x + v0.y + v0.z + v0.w) + (v1.x + v1.y + v1.z + v1.w);
    #pragma unroll
    for (int o = 16; o > 0; o >>= 1) s += __shfl_xor_sync(0xffffffffu, s, o);
    if (lane == 0) red[wid] = s;
    __syncthreads();
    if (tid < 32) {
        float t = (tid < 8) ? red[tid] : 0.f;
        #pragma unroll
        for (int o = 4; o > 0; o >>= 1) t += __shfl_xor_sync(0xffffffffu, t, o);
        if (tid == 0) red[0] = t;
    }
    __syncthreads();
    const float inv = 1.0f / red[0];

    __half2 h0 = __floats2half2_rn(v0.x * inv, v0.y * inv);
    __half2 h1 = __floats2half2_rn(v0.z * inv, v0.w * inv);
    __half2 h2 = __floats2half2_rn(v1.x * inv, v1.y * inv);
    __half2 h3 = __floats2half2_rn(v1.z * inv, v1.w * inv);
    ((__half2*)y)[tid * 2]             = h0;
    ((__half2*)y)[tid * 2 + 1]         = h1;
    ((__half2*)y)[(tid + 256) * 2]     = h2;
    ((__half2*)y)[(tid + 256) * 2 + 1] = h3;
}

// ---------------------------------------------------------------------------
// Launch
// ---------------------------------------------------------------------------
extern "C" void kernel_launch(void* const* d_in, const int* in_sizes, int n_in,
                              void* d_out, int out_size) {
    const float* Q  = (const float*)d_in[0];
    const float* K  = (const float*)d_in[1];
    const float* V  = (const float*)d_in[2];
    const float* W1 = (const float*)d_in[3];
    const float* b1 = (const float*)d_in[4];
    const float* W2 = (const float*)d_in[5];
    const float* b2 = (const float*)d_in[6];
    float* out = (float*)d_out;

    float *scores;
    __half *hh, *w1t, *w2t, *kt, *kw1t, *qh, *vt;
    cudaGetSymbolAddress((void**)&scores, g_scores);
    cudaGetSymbolAddress((void**)&hh, g_h_h);
    cudaGetSymbolAddress((void**)&w1t, g_w1t_h);
    cudaGetSymbolAddress((void**)&w2t, g_w2t_h);
    cudaGetSymbolAddress((void**)&kt, g_kt_h);
    cudaGetSymbolAddress((void**)&kw1t, g_kw1t_h);
    cudaGetSymbolAddress((void**)&qh, g_q_h);
    cudaGetSymbolAddress((void**)&vt, g_vt_h);

    cudaFuncSetAttribute(mma_gemm_h<2, false, false>,
                         cudaFuncAttributeMaxDynamicSharedMemorySize, GEMM_SMEM);
    cudaFuncSetAttribute(mma_gemm_h<1, true, true>,
                         cudaFuncAttributeMaxDynamicSharedMemorySize, GEMM_SMEM);
    cudaFuncSetAttribute(mma_gemm_h<0, false, true>,
                         cudaFuncAttributeMaxDynamicSharedMemorySize, GEMM_SMEM);
    cudaFuncSetAttribute(av_mma,
                         cudaFuncAttributeMaxDynamicSharedMemorySize, AV_SMEM);

    // 0) fp16 operands
    transpose_h<<<dim3(H_ / 32, S_ / 32, 1), dim3(32, 8)>>>(W1, w1t, S_, H_, 0, 0);
    transpose_h<<<dim3(S_ / 32, H_ / 32, 1), dim3(32, 8)>>>(W2, w2t, H_, S_, 0, 0);
    transpose_h<<<dim3(D_ / 32, S_ / 32, B_), dim3(32, 8)>>>(
        K, kt, S_, D_, (size_t)S_ * D_, (size_t)D_ * S_);
    transpose_h<<<dim3(D_ / 32, S_ / 32, B_), dim3(32, 8)>>>(
        V, vt, S_, D_, (size_t)S_ * D_, (size_t)D_ * S_);
    conv_h<<<(B_ * S_ * D_ / 4 + 255) / 256, 256>>>(Q, qh, B_ * S_ * D_ / 4);

    // 1) kw1t = fp16((K^T @ W1)/8), stored transposed per batch [4096,64]
    mma_gemm_h<2, false, false><<<dim3(H_ / BN, (B_ * D_) / BM, 1), 256, GEMM_SMEM>>>(
        kt, w1t, nullptr, kw1t, B_ * D_, H_, S_, 0.125f, 0, 0, 0);

    // 2) h = fp16(relu(Q @ KW1 + b1)) per batch; Bt = kw1t [4096,64]
    mma_gemm_h<1, true, true><<<dim3(H_ / BN, S_ / BM, B_), 256, GEMM_SMEM>>>(
        qh, kw1t, b1, hh, S_, H_, D_, 1.0f,
        (size_t)S_ * D_, (size_t)H_ * D_, (size_t)S_ * H_);

    // 3) adjusted = h @ W2 + b2 -> scores (fp32); Bt = W2^T [2048,4096]
    mma_gemm_h<0, false, true><<<dim3(S_ / BN, S_ / BM, B_), 256, GEMM_SMEM>>>(
        hh, w2t, b2, scores, S_, S_, H_, 1.0f,
        (size_t)S_ * H_, 0, (size_t)S_ * S_);

    // 4) softmax rows: fp32 logits -> fp16 attn (into hh, free after GEMM3)
    softmax_h_kernel<<<B_ * S_, 256>>>(scores, hh);

    // 5) out = attn @ V  (tensor cores)
    av_mma<<<dim3(1, S_ / BM, B_), 256, AV_SMEM>>>(hh, vt, out);
}